// round 13
// baseline (speedup 1.0000x reference)
#include <cuda_runtime.h>
#include <cuda_fp16.h>
#include <math.h>

// Problem constants
#define NB 4
#define NH 4
#define NS 4096
#define NDH 128
#define ND 512
#define NM (NB*NS)
#define QSZW (NB*NH*NS*NDH/2)   // words per Q/K/V tensor

#define LOG2E 1.44269504088896f

// Scratch (device globals — no allocation allowed). fp16 packed as half2.
__device__ __align__(16) unsigned g_xh[NM*ND/2];        // x fp16 [16384,512]
__device__ __align__(16) unsigned g_wh[4*ND*ND/2];      // weights fp16 (q,k,v,o)
__device__ __align__(16) unsigned g_qkv[3*QSZW];        // Q|K|V [B,H,S,DH]
__device__ __align__(16) unsigned g_oh[NM*ND/2];        // attn out fp16 [B*S,512]

__device__ __forceinline__ void mma_f16(
    float& d0, float& d1, float& d2, float& d3,
    unsigned a0, unsigned a1, unsigned a2, unsigned a3,
    unsigned b0, unsigned b1)
{
    asm volatile(
        "mma.sync.aligned.m16n8k16.row.col.f32.f16.f16.f32 "
        "{%0,%1,%2,%3}, {%4,%5,%6,%7}, {%8,%9}, {%0,%1,%2,%3};\n"
        : "+f"(d0), "+f"(d1), "+f"(d2), "+f"(d3)
        : "r"(a0), "r"(a1), "r"(a2), "r"(a3), "r"(b0), "r"(b1));
}
__device__ __forceinline__ void ldsm_x4(
    unsigned& r0, unsigned& r1, unsigned& r2, unsigned& r3, unsigned addr)
{
    asm volatile("ldmatrix.sync.aligned.m8n8.x4.shared.b16 {%0,%1,%2,%3}, [%4];"
        : "=r"(r0), "=r"(r1), "=r"(r2), "=r"(r3) : "r"(addr));
}
__device__ __forceinline__ void ldsm_x4_t(
    unsigned& r0, unsigned& r1, unsigned& r2, unsigned& r3, unsigned addr)
{
    asm volatile("ldmatrix.sync.aligned.m8n8.x4.trans.shared.b16 {%0,%1,%2,%3}, [%4];"
        : "=r"(r0), "=r"(r1), "=r"(r2), "=r"(r3) : "r"(addr));
}
__device__ __forceinline__ void cp16(unsigned dst, const void* src) {
    asm volatile("cp.async.cg.shared.global [%0], [%1], 16;" :: "r"(dst), "l"(src));
}

// ---------------------------------------------------------------------------
// Prep: f32 -> fp16. One kernel for x; one 4-way kernel for all weights.
// ---------------------------------------------------------------------------
__global__ __launch_bounds__(256) void cvt_f16(
    const float4* __restrict__ src, uint2* __restrict__ hi, int n4)
{
    int i = blockIdx.x * 256 + threadIdx.x;
    if (i >= n4) return;
    float4 v = src[i];
    __half2 h01 = __floats2half2_rn(v.x, v.y);
    __half2 h23 = __floats2half2_rn(v.z, v.w);
    hi[i] = make_uint2(*(unsigned*)&h01, *(unsigned*)&h23);
}
__global__ __launch_bounds__(256) void cvt_w4(
    const float4* __restrict__ wq, const float4* __restrict__ wk,
    const float4* __restrict__ wv, const float4* __restrict__ wo,
    uint2* __restrict__ hi, int n4)
{
    int widx = blockIdx.y;
    const float4* src = (widx == 0) ? wq : (widx == 1) ? wk : (widx == 2) ? wv : wo;
    int i = blockIdx.x * 256 + threadIdx.x;
    if (i >= n4) return;
    float4 v = src[i];
    __half2 h01 = __floats2half2_rn(v.x, v.y);
    __half2 h23 = __floats2half2_rn(v.z, v.w);
    hi[(size_t)widx * n4 + i] = make_uint2(*(unsigned*)&h01, *(unsigned*)&h23);
}

// ---------------------------------------------------------------------------
// Pure fp16 tensor-core GEMM, 2 CTAs/SM. (unchanged from R10/R11)
// ---------------------------------------------------------------------------
#define Q1A_STR 20
#define Q1W_STR 68
#define Q1BUF_A (128*Q1A_STR)
#define Q1BUF_W (32*Q1W_STR)
#define Q1BUF   (Q1BUF_A + Q1BUF_W)
#define Q1SM_WORDS (2*Q1BUF)

__global__ __launch_bounds__(256, 2) void gemm_f16(
    const unsigned* __restrict__ Ahg, const unsigned* __restrict__ Whg,
    void* __restrict__ out, float qscale, int mode)
{
    extern __shared__ unsigned smq[];
    const int t = threadIdx.x;
    const int rbase = blockIdx.x * 128;
    int widx, cbase;
    if (mode == 0) { widx = blockIdx.y >> 2; cbase = (blockIdx.y & 3) * 128; }
    else           { widx = 0; cbase = blockIdx.y * 128; }
    const unsigned* Whp = Whg + (size_t)widx * (ND * ND / 2);
    const float scl = (mode == 0 && widx == 0) ? qscale : 1.0f;
    const int cw0 = cbase >> 1;
    const int w = t >> 5, lane = t & 31;
    const int g = lane >> 2, q = lane & 3;
    const int wm = w >> 1, wn = w & 1;

    unsigned smb;
    asm("{ .reg .u64 x; cvta.to.shared.u64 x, %1; cvt.u32.u64 %0, x; }"
        : "=r"(smb) : "l"(smq));

    const int arow = (lane & 7) + ((lane & 8) ? 8 : 0);
    const int asel = (lane & 16) ? 4 : 0;

    float acc[2][8][4];
    #pragma unroll
    for (int mi = 0; mi < 2; mi++)
        #pragma unroll
        for (int j = 0; j < 8; j++)
            #pragma unroll
            for (int c = 0; c < 4; c++) acc[mi][j][c] = 0.f;

    #pragma unroll
    for (int it = 0; it < 2; it++) {
        int idx = it * 256 + t;
        int r = idx >> 2, c = (idx & 3) * 4;
        cp16(smb + (r * Q1A_STR + c) * 4, Ahg + (size_t)(rbase + r) * 256 + c);
        int rw = idx >> 4, cwt = (idx & 15) * 4;
        cp16(smb + (Q1BUF_A + rw * Q1W_STR + cwt) * 4, Whp + (size_t)rw * 256 + cw0 + cwt);
    }
    asm volatile("cp.async.commit_group;");

    for (int kt = 0; kt < 16; kt++) {
        if (kt < 15) {
            int buf = (kt + 1) & 1;
            #pragma unroll
            for (int it = 0; it < 2; it++) {
                int idx = it * 256 + t;
                int r = idx >> 2, c = (idx & 3) * 4;
                cp16(smb + (buf * Q1BUF + r * Q1A_STR + c) * 4,
                     Ahg + (size_t)(rbase + r) * 256 + (kt + 1) * 16 + c);
                int rw = idx >> 4, cwt = (idx & 15) * 4;
                cp16(smb + (buf * Q1BUF + Q1BUF_A + rw * Q1W_STR + cwt) * 4,
                     Whp + (size_t)((kt + 1) * 32 + rw) * 256 + cw0 + cwt);
            }
            asm volatile("cp.async.commit_group;");
            asm volatile("cp.async.wait_group 1;");
        } else {
            asm volatile("cp.async.wait_group 0;");
        }
        __syncthreads();

        const int buf = kt & 1;
        const unsigned abase = smb + (buf * Q1BUF + (32 * wm + arow) * Q1A_STR + asel) * 4;
        const unsigned bbase = smb + (buf * Q1BUF + Q1BUF_A + arow * Q1W_STR + asel) * 4
                               + wn * 128;
        #pragma unroll
        for (int ks = 0; ks < 2; ks++) {
            unsigned ah[2][4];
            #pragma unroll
            for (int mi = 0; mi < 2; mi++)
                ldsm_x4(ah[mi][0], ah[mi][1], ah[mi][2], ah[mi][3],
                        abase + mi * (16 * Q1A_STR * 4) + ks * 32);
            #pragma unroll
            for (int jp = 0; jp < 4; jp++) {
                unsigned bh0, bh1, bh2, bh3;
                ldsm_x4_t(bh0, bh1, bh2, bh3, bbase + ks * (16 * Q1W_STR * 4) + jp * 32);
                #pragma unroll
                for (int mi = 0; mi < 2; mi++) {
                    float* a0 = acc[mi][2 * jp];
                    float* a1 = acc[mi][2 * jp + 1];
                    mma_f16(a0[0], a0[1], a0[2], a0[3],
                            ah[mi][0], ah[mi][1], ah[mi][2], ah[mi][3], bh0, bh1);
                    mma_f16(a1[0], a1[1], a1[2], a1[3],
                            ah[mi][0], ah[mi][1], ah[mi][2], ah[mi][3], bh2, bh3);
                }
            }
        }
        __syncthreads();
    }

    #pragma unroll
    for (int mi = 0; mi < 2; mi++) {
        #pragma unroll
        for (int j = 0; j < 8; j++) {
            int row0 = rbase + 32 * wm + 16 * mi + g;
            int n = cbase + 64 * wn + 8 * j + 2 * q;
            float v0 = acc[mi][j][0] * scl, v1 = acc[mi][j][1] * scl;
            float v2 = acc[mi][j][2] * scl, v3 = acc[mi][j][3] * scl;
            if (mode == 0) {
                __half2 h0 = __floats2half2_rn(v0, v1);
                __half2 h1 = __floats2half2_rn(v2, v3);
                unsigned* oh = (unsigned*)out + (size_t)widx * QSZW;
                int head = n >> 7, e = n & 127;
                int b0i = row0 >> 12, s0 = row0 & 4095;
                int b1i = (row0 + 8) >> 12, s1 = (row0 + 8) & 4095;
                oh[(((size_t)(b0i * NH + head) * NS + s0) << 6) + (e >> 1)] = *(unsigned*)&h0;
                oh[(((size_t)(b1i * NH + head) * NS + s1) << 6) + (e >> 1)] = *(unsigned*)&h1;
            } else {
                float* of = (float*)out;
                *(float2*)&of[(size_t)row0 * 512 + n] = make_float2(v0, v1);
                *(float2*)&of[(size_t)(row0 + 8) * 512 + n] = make_float2(v2, v3);
            }
        }
    }
}

// ---------------------------------------------------------------------------
// fp16 flash attention (R11 mainloop) + PAIRED Q-TILES for load balance:
// grid (16, 16); CTA x handles q-blocks (31-x) then (x): constant 66
// tile-units per CTA -> one balanced wave of 256 equal CTAs.
// ---------------------------------------------------------------------------
#define SM2_Q   0
#define SM2_KV  (128*68)
#define KVBUF   (2*64*68)
#define SM2_BIAS (SM2_KV + 2*KVBUF)
#define ATTN_SMEM_WORDS (SM2_BIAS + 256)
#define ONES2 0x3C003C00u

__global__ __launch_bounds__(256, 2) void attn_f16(
    const float* __restrict__ rel_row, const float* __restrict__ rel_col)
{
    extern __shared__ unsigned sm2[];
    const int t = threadIdx.x;
    const int bh = blockIdx.y;
    const int h = bh & 3, b = bh >> 2;
    const int w = t >> 5, lane = t & 31;
    const int g = lane >> 2, q = lane & 3;
    const int base_r = 16 * w;
    const int half_ = (w >= 4) ? 1 : 0;

    float* srow = (float*)(sm2 + SM2_BIAS);
    float* scol = srow + 128;
    if (t < 128) srow[t] = rel_row[h * 128 + t] * LOG2E;
    else         scol[t - 128] = rel_col[h * 128 + t - 128] * LOG2E;

    const unsigned* Kg0 = g_qkv + QSZW + (size_t)bh * NS * 64;
    const unsigned* Vg0 = g_qkv + 2 * QSZW + (size_t)bh * NS * 64;

    unsigned smb;
    asm("{ .reg .u64 x; cvta.to.shared.u64 x, %1; cvt.u32.u64 %0, x; }"
        : "=r"(smb) : "l"(sm2));

    const int arow = (lane & 7) + ((lane & 8) ? 8 : 0);
    const int asel = (lane & 16) ? 4 : 0;
    const int brow = (lane & 7) + ((lane & 16) ? 8 : 0);
    const int bsel = (lane & 8) ? 4 : 0;
    const unsigned q_ad = smb + (SM2_Q + (base_r + arow) * 68 + asel) * 4;
    const int qcol0 = (base_r & 63) + g;
    const int qcol1 = qcol0 + 8;

    for (int pass = 0; pass < 2; pass++) {
        const int qbx = pass ? (int)blockIdx.x : 31 - (int)blockIdx.x;
        const int kb_diag = 2 * qbx + half_;
        const int nkb = 2 * qbx + 2;

        const unsigned* Qg = g_qkv + ((size_t)bh * NS + (size_t)qbx * 128) * 64;
        #pragma unroll
        for (int it = 0; it < 8; it++) {
            int idx = it * 256 + t;
            int r = idx >> 4, u = (idx & 15) * 4;
            *(uint4*)&sm2[SM2_Q + r * 68 + u] = *(const uint4*)&Qg[r * 64 + u];
        }

        // KV tile 0 prefetch
        #pragma unroll
        for (int it = 0; it < 4; it++) {
            int idx = it * 256 + t;
            int r = idx >> 4, u = (idx & 15) * 4;
            cp16(smb + (SM2_KV + r * 68 + u) * 4, &Kg0[r * 64 + u]);
            cp16(smb + (SM2_KV + 64 * 68 + r * 68 + u) * 4, &Vg0[r * 64 + u]);
        }
        asm volatile("cp.async.commit_group;");

        float lacc[4] = {0.f, 0.f, 0.f, 0.f};
        float oacc[16][4];
        #pragma unroll
        for (int jd = 0; jd < 16; jd++)
            #pragma unroll
            for (int c = 0; c < 4; c++) oacc[jd][c] = 0.f;

        for (int i = 0; i < nkb; i++) {
            if (i + 1 < nkb) {
                int nb = (i + 1) & 1;
                const unsigned* Kg = Kg0 + (size_t)(i + 1) * 64 * 64;
                const unsigned* Vg = Vg0 + (size_t)(i + 1) * 64 * 64;
                #pragma unroll
                for (int it = 0; it < 4; it++) {
                    int idx = it * 256 + t;
                    int r = idx >> 4, u = (idx & 15) * 4;
                    cp16(smb + (SM2_KV + nb * KVBUF + r * 68 + u) * 4, &Kg[r * 64 + u]);
                    cp16(smb + (SM2_KV + nb * KVBUF + 64 * 68 + r * 68 + u) * 4, &Vg[r * 64 + u]);
                }
                asm volatile("cp.async.commit_group;");
                asm volatile("cp.async.wait_group 1;");
            } else {
                asm volatile("cp.async.wait_group 0;");
            }
            __syncthreads();

            if (i <= kb_diag) {
                const int buf = i & 1;
                const unsigned k_ad = smb + (SM2_KV + buf * KVBUF + brow * 68 + bsel) * 4;
                const unsigned v_ad = smb + (SM2_KV + buf * KVBUF + 64 * 68 + arow * 68 + asel) * 4;
                const float rowb = srow[63 + i - kb_diag];
                const bool diag = (i == kb_diag);

                #pragma unroll
                for (int hf = 0; hf < 2; hf++) {
                    // ---- S(half) = Q K^T over n-tiles j = 4hf..4hf+3 ----
                    float sacc[4][4];
                    #pragma unroll
                    for (int j = 0; j < 4; j++)
                        #pragma unroll
                        for (int c = 0; c < 4; c++) sacc[j][c] = 0.f;

                    #pragma unroll
                    for (int ks = 0; ks < 8; ks++) {
                        unsigned a0, a1, a2, a3;
                        ldsm_x4(a0, a1, a2, a3, q_ad + ks * 32);
                        #pragma unroll
                        for (int jp = 0; jp < 2; jp++) {
                            int jpp = 2 * hf + jp;
                            unsigned b0, b1, b2, b3;
                            ldsm_x4(b0, b1, b2, b3, k_ad + jpp * 4352 + ks * 32);
                            mma_f16(sacc[2*jp][0], sacc[2*jp][1], sacc[2*jp][2], sacc[2*jp][3],
                                    a0, a1, a2, a3, b0, b1);
                            mma_f16(sacc[2*jp+1][0], sacc[2*jp+1][1], sacc[2*jp+1][2], sacc[2*jp+1][3],
                                    a0, a1, a2, a3, b2, b3);
                        }
                    }

                    // ---- bias + mask + ex2.f16x2; P(half) into A-fragments ----
                    unsigned ph0[4], ph1[4];
                    #pragma unroll
                    for (int j = 0; j < 4; j++) {
                        int jj = 4 * hf + j;
                        int n0 = 8 * jj + 2 * q, n1 = n0 + 1;
                        float s0a = sacc[j][0] + rowb + scol[63 + n0 - qcol0];
                        float s0b = sacc[j][1] + rowb + scol[63 + n1 - qcol0];
                        float s1a = sacc[j][2] + rowb + scol[63 + n0 - qcol1];
                        float s1b = sacc[j][3] + rowb + scol[63 + n1 - qcol1];
                        if (diag) {
                            if (n0 > qcol0) s0a = -60000.f;
                            if (n1 > qcol0) s0b = -60000.f;
                            if (n0 > qcol1) s1a = -60000.f;
                            if (n1 > qcol1) s1b = -60000.f;
                        }
                        __half2 e0 = h2exp2(__floats2half2_rn(s0a, s0b));
                        __half2 e1 = h2exp2(__floats2half2_rn(s1a, s1b));
                        ph0[j] = *(unsigned*)&e0;
                        ph1[j] = *(unsigned*)&e1;
                    }

                    // ---- O += P V over ks = 2hf, 2hf+1; l += P @ ones ----
                    #pragma unroll
                    for (int k2 = 0; k2 < 2; k2++) {
                        int ks = 2 * hf + k2;
                        unsigned pa0 = ph0[2*k2], pa1 = ph1[2*k2];
                        unsigned pa2 = ph0[2*k2+1], pa3 = ph1[2*k2+1];
                        mma_f16(lacc[0], lacc[1], lacc[2], lacc[3],
                                pa0, pa1, pa2, pa3, ONES2, ONES2);
                        #pragma unroll
                        for (int jdp = 0; jdp < 8; jdp++) {
                            unsigned vb0, vb1, vb2, vb3;
                            ldsm_x4_t(vb0, vb1, vb2, vb3, v_ad + ks * 4352 + jdp * 32);
                            mma_f16(oacc[2*jdp][0], oacc[2*jdp][1], oacc[2*jdp][2], oacc[2*jdp][3],
                                    pa0, pa1, pa2, pa3, vb0, vb1);
                            mma_f16(oacc[2*jdp+1][0], oacc[2*jdp+1][1], oacc[2*jdp+1][2], oacc[2*jdp+1][3],
                                    pa0, pa1, pa2, pa3, vb2, vb3);
                        }
                    }
                }
            }
            __syncthreads();
        }

        // ---- normalize + fp16 store ----
        const float inv0 = 1.f / lacc[0], inv1 = 1.f / lacc[2];
        const int qg0 = qbx * 128 + base_r + g;
        const int roww0 = ((b * NS + qg0) * ND + h * NDH) >> 1;
        const int roww1 = roww0 + 4 * ND;     // +8 rows
        #pragma unroll
        for (int jd = 0; jd < 16; jd++) {
            __half2 hh0 = __floats2half2_rn(oacc[jd][0] * inv0, oacc[jd][1] * inv0);
            __half2 hh1 = __floats2half2_rn(oacc[jd][2] * inv1, oacc[jd][3] * inv1);
            g_oh[roww0 + 4 * jd + q] = *(unsigned*)&hh0;
            g_oh[roww1 + 4 * jd + q] = *(unsigned*)&hh1;
        }
    }
}

// ---------------------------------------------------------------------------
extern "C" void kernel_launch(void* const* d_in, const int* in_sizes, int n_in,
                              void* d_out, int out_size)
{
    const float* x       = (const float*)d_in[0];
    const float* wq      = (const float*)d_in[1];
    const float* wk      = (const float*)d_in[2];
    const float* wv      = (const float*)d_in[3];
    const float* wo      = (const float*)d_in[4];
    const float* rel_row = (const float*)d_in[5];
    const float* rel_col = (const float*)d_in[6];
    float* out = (float*)d_out;

    unsigned *xh, *wh, *qkv, *oh;
    cudaGetSymbolAddress((void**)&xh, g_xh);
    cudaGetSymbolAddress((void**)&wh, g_wh);
    cudaGetSymbolAddress((void**)&qkv, g_qkv);
    cudaGetSymbolAddress((void**)&oh, g_oh);

    static int smem_set = 0;
    if (!smem_set) {
        cudaFuncSetAttribute(attn_f16, cudaFuncAttributeMaxDynamicSharedMemorySize,
                             ATTN_SMEM_WORDS * (int)sizeof(unsigned));
        cudaFuncSetAttribute(gemm_f16, cudaFuncAttributeMaxDynamicSharedMemorySize,
                             Q1SM_WORDS * (int)sizeof(unsigned));
        smem_set = 1;
    }

    const int WW = ND * ND / 2;
    const int xn4 = NM * ND / 4;
    const int wn4 = ND * ND / 4;

    cvt_f16<<<(xn4 + 255) / 256, 256>>>((const float4*)x, (uint2*)xh, xn4);
    cvt_w4<<<dim3((wn4 + 255) / 256, 4), 256>>>(
        (const float4*)wq, (const float4*)wk, (const float4*)wv, (const float4*)wo,
        (uint2*)wh, wn4);

    const float qscale = 0.08838834764831845f * LOG2E;  // 1/sqrt(128) * log2(e)
    size_t gsmem = Q1SM_WORDS * sizeof(unsigned);

    gemm_f16<<<dim3(NM / 128, 12), 256, gsmem>>>(xh, wh, qkv, qscale, 0);

    attn_f16<<<dim3(16, NB * NH), 256,
               ATTN_SMEM_WORDS * sizeof(unsigned)>>>(rel_row, rel_col);

    gemm_f16<<<dim3(NM / 128, 4), 256, gsmem>>>(oh, wh + 3 * WW, out, 1.0f, 1);
}

// round 14
// speedup vs baseline: 1.3266x; 1.3266x over previous
#include <cuda_runtime.h>
#include <cuda_fp16.h>
#include <math.h>

// Problem constants
#define NB 4
#define NH 4
#define NS 4096
#define NDH 128
#define ND 512
#define NM (NB*NS)
#define QSZW (NB*NH*NS*NDH/2)   // words per Q/K/V tensor

#define LOG2E 1.44269504088896f

// Scratch (device globals — no allocation allowed). fp16 packed as half2.
__device__ __align__(16) unsigned g_xh[NM*ND/2];        // x fp16 [16384,512]
__device__ __align__(16) unsigned g_wh[4*ND*ND/2];      // weights fp16 (q,k,v,o)
__device__ __align__(16) unsigned g_qkv[3*QSZW];        // Q|K|V [B,H,S,DH]
__device__ __align__(16) unsigned g_oh[NM*ND/2];        // attn out fp16 [B*S,512]

__device__ __forceinline__ void mma_f16(
    float& d0, float& d1, float& d2, float& d3,
    unsigned a0, unsigned a1, unsigned a2, unsigned a3,
    unsigned b0, unsigned b1)
{
    asm volatile(
        "mma.sync.aligned.m16n8k16.row.col.f32.f16.f16.f32 "
        "{%0,%1,%2,%3}, {%4,%5,%6,%7}, {%8,%9}, {%0,%1,%2,%3};\n"
        : "+f"(d0), "+f"(d1), "+f"(d2), "+f"(d3)
        : "r"(a0), "r"(a1), "r"(a2), "r"(a3), "r"(b0), "r"(b1));
}
__device__ __forceinline__ void ldsm_x4(
    unsigned& r0, unsigned& r1, unsigned& r2, unsigned& r3, unsigned addr)
{
    asm volatile("ldmatrix.sync.aligned.m8n8.x4.shared.b16 {%0,%1,%2,%3}, [%4];"
        : "=r"(r0), "=r"(r1), "=r"(r2), "=r"(r3) : "r"(addr));
}
__device__ __forceinline__ void ldsm_x4_t(
    unsigned& r0, unsigned& r1, unsigned& r2, unsigned& r3, unsigned addr)
{
    asm volatile("ldmatrix.sync.aligned.m8n8.x4.trans.shared.b16 {%0,%1,%2,%3}, [%4];"
        : "=r"(r0), "=r"(r1), "=r"(r2), "=r"(r3) : "r"(addr));
}
__device__ __forceinline__ void cp16(unsigned dst, const void* src) {
    asm volatile("cp.async.cg.shared.global [%0], [%1], 16;" :: "r"(dst), "l"(src));
}

// ---------------------------------------------------------------------------
// Prep: f32 -> fp16. One kernel for x; one 4-way kernel for all weights.
// ---------------------------------------------------------------------------
__global__ __launch_bounds__(256) void cvt_f16(
    const float4* __restrict__ src, uint2* __restrict__ hi, int n4)
{
    int i = blockIdx.x * 256 + threadIdx.x;
    if (i >= n4) return;
    float4 v = src[i];
    __half2 h01 = __floats2half2_rn(v.x, v.y);
    __half2 h23 = __floats2half2_rn(v.z, v.w);
    hi[i] = make_uint2(*(unsigned*)&h01, *(unsigned*)&h23);
}
__global__ __launch_bounds__(256) void cvt_w4(
    const float4* __restrict__ wq, const float4* __restrict__ wk,
    const float4* __restrict__ wv, const float4* __restrict__ wo,
    uint2* __restrict__ hi, int n4)
{
    int widx = blockIdx.y;
    const float4* src = (widx == 0) ? wq : (widx == 1) ? wk : (widx == 2) ? wv : wo;
    int i = blockIdx.x * 256 + threadIdx.x;
    if (i >= n4) return;
    float4 v = src[i];
    __half2 h01 = __floats2half2_rn(v.x, v.y);
    __half2 h23 = __floats2half2_rn(v.z, v.w);
    hi[(size_t)widx * n4 + i] = make_uint2(*(unsigned*)&h01, *(unsigned*)&h23);
}

// ---------------------------------------------------------------------------
// Pure fp16 tensor-core GEMM, 2 CTAs/SM. (unchanged from R10/R11)
// ---------------------------------------------------------------------------
#define Q1A_STR 20
#define Q1W_STR 68
#define Q1BUF_A (128*Q1A_STR)
#define Q1BUF_W (32*Q1W_STR)
#define Q1BUF   (Q1BUF_A + Q1BUF_W)
#define Q1SM_WORDS (2*Q1BUF)

__global__ __launch_bounds__(256, 2) void gemm_f16(
    const unsigned* __restrict__ Ahg, const unsigned* __restrict__ Whg,
    void* __restrict__ out, float qscale, int mode)
{
    extern __shared__ unsigned smq[];
    const int t = threadIdx.x;
    const int rbase = blockIdx.x * 128;
    int widx, cbase;
    if (mode == 0) { widx = blockIdx.y >> 2; cbase = (blockIdx.y & 3) * 128; }
    else           { widx = 0; cbase = blockIdx.y * 128; }
    const unsigned* Whp = Whg + (size_t)widx * (ND * ND / 2);
    const float scl = (mode == 0 && widx == 0) ? qscale : 1.0f;
    const int cw0 = cbase >> 1;
    const int w = t >> 5, lane = t & 31;
    const int g = lane >> 2, q = lane & 3;
    const int wm = w >> 1, wn = w & 1;

    unsigned smb;
    asm("{ .reg .u64 x; cvta.to.shared.u64 x, %1; cvt.u32.u64 %0, x; }"
        : "=r"(smb) : "l"(smq));

    const int arow = (lane & 7) + ((lane & 8) ? 8 : 0);
    const int asel = (lane & 16) ? 4 : 0;

    float acc[2][8][4];
    #pragma unroll
    for (int mi = 0; mi < 2; mi++)
        #pragma unroll
        for (int j = 0; j < 8; j++)
            #pragma unroll
            for (int c = 0; c < 4; c++) acc[mi][j][c] = 0.f;

    #pragma unroll
    for (int it = 0; it < 2; it++) {
        int idx = it * 256 + t;
        int r = idx >> 2, c = (idx & 3) * 4;
        cp16(smb + (r * Q1A_STR + c) * 4, Ahg + (size_t)(rbase + r) * 256 + c);
        int rw = idx >> 4, cwt = (idx & 15) * 4;
        cp16(smb + (Q1BUF_A + rw * Q1W_STR + cwt) * 4, Whp + (size_t)rw * 256 + cw0 + cwt);
    }
    asm volatile("cp.async.commit_group;");

    for (int kt = 0; kt < 16; kt++) {
        if (kt < 15) {
            int buf = (kt + 1) & 1;
            #pragma unroll
            for (int it = 0; it < 2; it++) {
                int idx = it * 256 + t;
                int r = idx >> 2, c = (idx & 3) * 4;
                cp16(smb + (buf * Q1BUF + r * Q1A_STR + c) * 4,
                     Ahg + (size_t)(rbase + r) * 256 + (kt + 1) * 16 + c);
                int rw = idx >> 4, cwt = (idx & 15) * 4;
                cp16(smb + (buf * Q1BUF + Q1BUF_A + rw * Q1W_STR + cwt) * 4,
                     Whp + (size_t)((kt + 1) * 32 + rw) * 256 + cw0 + cwt);
            }
            asm volatile("cp.async.commit_group;");
            asm volatile("cp.async.wait_group 1;");
        } else {
            asm volatile("cp.async.wait_group 0;");
        }
        __syncthreads();

        const int buf = kt & 1;
        const unsigned abase = smb + (buf * Q1BUF + (32 * wm + arow) * Q1A_STR + asel) * 4;
        const unsigned bbase = smb + (buf * Q1BUF + Q1BUF_A + arow * Q1W_STR + asel) * 4
                               + wn * 128;
        #pragma unroll
        for (int ks = 0; ks < 2; ks++) {
            unsigned ah[2][4];
            #pragma unroll
            for (int mi = 0; mi < 2; mi++)
                ldsm_x4(ah[mi][0], ah[mi][1], ah[mi][2], ah[mi][3],
                        abase + mi * (16 * Q1A_STR * 4) + ks * 32);
            #pragma unroll
            for (int jp = 0; jp < 4; jp++) {
                unsigned bh0, bh1, bh2, bh3;
                ldsm_x4_t(bh0, bh1, bh2, bh3, bbase + ks * (16 * Q1W_STR * 4) + jp * 32);
                #pragma unroll
                for (int mi = 0; mi < 2; mi++) {
                    float* a0 = acc[mi][2 * jp];
                    float* a1 = acc[mi][2 * jp + 1];
                    mma_f16(a0[0], a0[1], a0[2], a0[3],
                            ah[mi][0], ah[mi][1], ah[mi][2], ah[mi][3], bh0, bh1);
                    mma_f16(a1[0], a1[1], a1[2], a1[3],
                            ah[mi][0], ah[mi][1], ah[mi][2], ah[mi][3], bh2, bh3);
                }
            }
        }
        __syncthreads();
    }

    #pragma unroll
    for (int mi = 0; mi < 2; mi++) {
        #pragma unroll
        for (int j = 0; j < 8; j++) {
            int row0 = rbase + 32 * wm + 16 * mi + g;
            int n = cbase + 64 * wn + 8 * j + 2 * q;
            float v0 = acc[mi][j][0] * scl, v1 = acc[mi][j][1] * scl;
            float v2 = acc[mi][j][2] * scl, v3 = acc[mi][j][3] * scl;
            if (mode == 0) {
                __half2 h0 = __floats2half2_rn(v0, v1);
                __half2 h1 = __floats2half2_rn(v2, v3);
                unsigned* oh = (unsigned*)out + (size_t)widx * QSZW;
                int head = n >> 7, e = n & 127;
                int b0i = row0 >> 12, s0 = row0 & 4095;
                int b1i = (row0 + 8) >> 12, s1 = (row0 + 8) & 4095;
                oh[(((size_t)(b0i * NH + head) * NS + s0) << 6) + (e >> 1)] = *(unsigned*)&h0;
                oh[(((size_t)(b1i * NH + head) * NS + s1) << 6) + (e >> 1)] = *(unsigned*)&h1;
            } else {
                float* of = (float*)out;
                *(float2*)&of[(size_t)row0 * 512 + n] = make_float2(v0, v1);
                *(float2*)&of[(size_t)(row0 + 8) * 512 + n] = make_float2(v2, v3);
            }
        }
    }
}

// ---------------------------------------------------------------------------
// fp16 flash attention (R11 structure: grid 512 heavy-first, n-half
// interleaving) + HALF-PERSISTENT Q: fragments for ks 0..3 (16 regs) loaded
// once per CTA; ks 4..7 via ldsm. Live set ~124 regs, per-tile LDSM 80->72.
// ---------------------------------------------------------------------------
#define SM2_Q   0
#define SM2_KV  (128*68)
#define KVBUF   (2*64*68)
#define SM2_BIAS (SM2_KV + 2*KVBUF)
#define ATTN_SMEM_WORDS (SM2_BIAS + 256)
#define ONES2 0x3C003C00u

__global__ __launch_bounds__(256, 2) void attn_f16(
    const float* __restrict__ rel_row, const float* __restrict__ rel_col)
{
    extern __shared__ unsigned sm2[];
    const int t = threadIdx.x;
    const int qbx = 31 - blockIdx.x;     // heavy CTAs first
    const int bh = blockIdx.y;
    const int h = bh & 3, b = bh >> 2;
    const int w = t >> 5, lane = t & 31;
    const int g = lane >> 2, q = lane & 3;
    const int base_r = 16 * w;
    const int half_ = (w >= 4) ? 1 : 0;
    const int kb_diag = 2 * qbx + half_;
    const int nkb = 2 * qbx + 2;

    float* srow = (float*)(sm2 + SM2_BIAS);
    float* scol = srow + 128;
    if (t < 128) srow[t] = rel_row[h * 128 + t] * LOG2E;
    else         scol[t - 128] = rel_col[h * 128 + t - 128] * LOG2E;

    const unsigned* Qg  = g_qkv + ((size_t)bh * NS + (size_t)qbx * 128) * 64;
    const unsigned* Kg0 = g_qkv + QSZW + (size_t)bh * NS * 64;
    const unsigned* Vg0 = g_qkv + 2 * QSZW + (size_t)bh * NS * 64;

    #pragma unroll
    for (int it = 0; it < 8; it++) {
        int idx = it * 256 + t;
        int r = idx >> 4, u = (idx & 15) * 4;
        *(uint4*)&sm2[SM2_Q + r * 68 + u] = *(const uint4*)&Qg[r * 64 + u];
    }

    unsigned smb;
    asm("{ .reg .u64 x; cvta.to.shared.u64 x, %1; cvt.u32.u64 %0, x; }"
        : "=r"(smb) : "l"(sm2));

    const int arow = (lane & 7) + ((lane & 8) ? 8 : 0);
    const int asel = (lane & 16) ? 4 : 0;
    const int brow = (lane & 7) + ((lane & 16) ? 8 : 0);
    const int bsel = (lane & 8) ? 4 : 0;
    const unsigned q_ad = smb + (SM2_Q + (base_r + arow) * 68 + asel) * 4;

    // KV tile 0 prefetch
    {
        #pragma unroll
        for (int it = 0; it < 4; it++) {
            int idx = it * 256 + t;
            int r = idx >> 4, u = (idx & 15) * 4;
            cp16(smb + (SM2_KV + r * 68 + u) * 4, &Kg0[r * 64 + u]);
            cp16(smb + (SM2_KV + 64 * 68 + r * 68 + u) * 4, &Vg0[r * 64 + u]);
        }
        asm volatile("cp.async.commit_group;");
    }

    // ---- half-persistent Q fragments (ks 0..3 resident, 16 regs) ----
    __syncthreads();
    unsigned qf[4][4];
    #pragma unroll
    for (int ks = 0; ks < 4; ks++)
        ldsm_x4(qf[ks][0], qf[ks][1], qf[ks][2], qf[ks][3], q_ad + ks * 32);

    float lacc[4] = {0.f, 0.f, 0.f, 0.f};
    float oacc[16][4];
    #pragma unroll
    for (int jd = 0; jd < 16; jd++)
        #pragma unroll
        for (int c = 0; c < 4; c++) oacc[jd][c] = 0.f;

    const int qcol0 = (base_r & 63) + g;
    const int qcol1 = qcol0 + 8;

    for (int i = 0; i < nkb; i++) {
        if (i + 1 < nkb) {
            int nb = (i + 1) & 1;
            const unsigned* Kg = Kg0 + (size_t)(i + 1) * 64 * 64;
            const unsigned* Vg = Vg0 + (size_t)(i + 1) * 64 * 64;
            #pragma unroll
            for (int it = 0; it < 4; it++) {
                int idx = it * 256 + t;
                int r = idx >> 4, u = (idx & 15) * 4;
                cp16(smb + (SM2_KV + nb * KVBUF + r * 68 + u) * 4, &Kg[r * 64 + u]);
                cp16(smb + (SM2_KV + nb * KVBUF + 64 * 68 + r * 68 + u) * 4, &Vg[r * 64 + u]);
            }
            asm volatile("cp.async.commit_group;");
            asm volatile("cp.async.wait_group 1;");
        } else {
            asm volatile("cp.async.wait_group 0;");
        }
        __syncthreads();

        if (i <= kb_diag) {
            const int buf = i & 1;
            const unsigned k_ad = smb + (SM2_KV + buf * KVBUF + brow * 68 + bsel) * 4;
            const unsigned v_ad = smb + (SM2_KV + buf * KVBUF + 64 * 68 + arow * 68 + asel) * 4;
            const float rowb = srow[63 + i - kb_diag];
            const bool diag = (i == kb_diag);

            #pragma unroll
            for (int hf = 0; hf < 2; hf++) {
                // ---- S(half) = Q K^T over n-tiles j = 4hf..4hf+3 ----
                float sacc[4][4];
                #pragma unroll
                for (int j = 0; j < 4; j++)
                    #pragma unroll
                    for (int c = 0; c < 4; c++) sacc[j][c] = 0.f;

                #pragma unroll
                for (int ks = 0; ks < 8; ks++) {
                    unsigned a0, a1, a2, a3;
                    if (ks < 4) {
                        a0 = qf[ks][0]; a1 = qf[ks][1]; a2 = qf[ks][2]; a3 = qf[ks][3];
                    } else {
                        ldsm_x4(a0, a1, a2, a3, q_ad + ks * 32);
                    }
                    #pragma unroll
                    for (int jp = 0; jp < 2; jp++) {
                        int jpp = 2 * hf + jp;
                        unsigned b0, b1, b2, b3;
                        ldsm_x4(b0, b1, b2, b3, k_ad + jpp * 4352 + ks * 32);
                        mma_f16(sacc[2*jp][0], sacc[2*jp][1], sacc[2*jp][2], sacc[2*jp][3],
                                a0, a1, a2, a3, b0, b1);
                        mma_f16(sacc[2*jp+1][0], sacc[2*jp+1][1], sacc[2*jp+1][2], sacc[2*jp+1][3],
                                a0, a1, a2, a3, b2, b3);
                    }
                }

                // ---- bias + mask + ex2.f16x2; P(half) into A-fragments ----
                unsigned ph0[4], ph1[4];
                #pragma unroll
                for (int j = 0; j < 4; j++) {
                    int jj = 4 * hf + j;
                    int n0 = 8 * jj + 2 * q, n1 = n0 + 1;
                    float s0a = sacc[j][0] + rowb + scol[63 + n0 - qcol0];
                    float s0b = sacc[j][1] + rowb + scol[63 + n1 - qcol0];
                    float s1a = sacc[j][2] + rowb + scol[63 + n0 - qcol1];
                    float s1b = sacc[j][3] + rowb + scol[63 + n1 - qcol1];
                    if (diag) {
                        if (n0 > qcol0) s0a = -60000.f;
                        if (n1 > qcol0) s0b = -60000.f;
                        if (n0 > qcol1) s1a = -60000.f;
                        if (n1 > qcol1) s1b = -60000.f;
                    }
                    __half2 e0 = h2exp2(__floats2half2_rn(s0a, s0b));
                    __half2 e1 = h2exp2(__floats2half2_rn(s1a, s1b));
                    ph0[j] = *(unsigned*)&e0;
                    ph1[j] = *(unsigned*)&e1;
                }

                // ---- O += P V over ks = 2hf, 2hf+1; l += P @ ones ----
                #pragma unroll
                for (int k2 = 0; k2 < 2; k2++) {
                    int ks = 2 * hf + k2;
                    unsigned pa0 = ph0[2*k2], pa1 = ph1[2*k2];
                    unsigned pa2 = ph0[2*k2+1], pa3 = ph1[2*k2+1];
                    mma_f16(lacc[0], lacc[1], lacc[2], lacc[3],
                            pa0, pa1, pa2, pa3, ONES2, ONES2);
                    #pragma unroll
                    for (int jdp = 0; jdp < 8; jdp++) {
                        unsigned vb0, vb1, vb2, vb3;
                        ldsm_x4_t(vb0, vb1, vb2, vb3, v_ad + ks * 4352 + jdp * 32);
                        mma_f16(oacc[2*jdp][0], oacc[2*jdp][1], oacc[2*jdp][2], oacc[2*jdp][3],
                                pa0, pa1, pa2, pa3, vb0, vb1);
                        mma_f16(oacc[2*jdp+1][0], oacc[2*jdp+1][1], oacc[2*jdp+1][2], oacc[2*jdp+1][3],
                                pa0, pa1, pa2, pa3, vb2, vb3);
                    }
                }
            }
        }
        __syncthreads();
    }

    // ---- normalize + fp16 store ----
    const float inv0 = 1.f / lacc[0], inv1 = 1.f / lacc[2];
    const int qg0 = qbx * 128 + base_r + g;
    const int roww0 = ((b * NS + qg0) * ND + h * NDH) >> 1;
    const int roww1 = roww0 + 4 * ND;     // +8 rows
    #pragma unroll
    for (int jd = 0; jd < 16; jd++) {
        __half2 hh0 = __floats2half2_rn(oacc[jd][0] * inv0, oacc[jd][1] * inv0);
        __half2 hh1 = __floats2half2_rn(oacc[jd][2] * inv1, oacc[jd][3] * inv1);
        g_oh[roww0 + 4 * jd + q] = *(unsigned*)&hh0;
        g_oh[roww1 + 4 * jd + q] = *(unsigned*)&hh1;
    }
}

// ---------------------------------------------------------------------------
extern "C" void kernel_launch(void* const* d_in, const int* in_sizes, int n_in,
                              void* d_out, int out_size)
{
    const float* x       = (const float*)d_in[0];
    const float* wq      = (const float*)d_in[1];
    const float* wk      = (const float*)d_in[2];
    const float* wv      = (const float*)d_in[3];
    const float* wo      = (const float*)d_in[4];
    const float* rel_row = (const float*)d_in[5];
    const float* rel_col = (const float*)d_in[6];
    float* out = (float*)d_out;

    unsigned *xh, *wh, *qkv, *oh;
    cudaGetSymbolAddress((void**)&xh, g_xh);
    cudaGetSymbolAddress((void**)&wh, g_wh);
    cudaGetSymbolAddress((void**)&qkv, g_qkv);
    cudaGetSymbolAddress((void**)&oh, g_oh);

    static int smem_set = 0;
    if (!smem_set) {
        cudaFuncSetAttribute(attn_f16, cudaFuncAttributeMaxDynamicSharedMemorySize,
                             ATTN_SMEM_WORDS * (int)sizeof(unsigned));
        cudaFuncSetAttribute(gemm_f16, cudaFuncAttributeMaxDynamicSharedMemorySize,
                             Q1SM_WORDS * (int)sizeof(unsigned));
        smem_set = 1;
    }

    const int WW = ND * ND / 2;
    const int xn4 = NM * ND / 4;
    const int wn4 = ND * ND / 4;

    cvt_f16<<<(xn4 + 255) / 256, 256>>>((const float4*)x, (uint2*)xh, xn4);
    cvt_w4<<<dim3((wn4 + 255) / 256, 4), 256>>>(
        (const float4*)wq, (const float4*)wk, (const float4*)wv, (const float4*)wo,
        (uint2*)wh, wn4);

    const float qscale = 0.08838834764831845f * LOG2E;  // 1/sqrt(128) * log2(e)
    size_t gsmem = Q1SM_WORDS * sizeof(unsigned);

    gemm_f16<<<dim3(NM / 128, 12), 256, gsmem>>>(xh, wh, qkv, qscale, 0);

    attn_f16<<<dim3(NS / 128, NB * NH), 256,
               ATTN_SMEM_WORDS * sizeof(unsigned)>>>(rel_row, rel_col);

    gemm_f16<<<dim3(NM / 128, 4), 256, gsmem>>>(oh, wh + 3 * WW, out, 1.0f, 1);
}

// round 15
// speedup vs baseline: 1.3631x; 1.0275x over previous
#include <cuda_runtime.h>
#include <cuda_fp16.h>
#include <math.h>

// Problem constants
#define NB 4
#define NH 4
#define NS 4096
#define NDH 128
#define ND 512
#define NM (NB*NS)
#define QSZW (NB*NH*NS*NDH/2)   // words per Q/K/V tensor

#define LOG2E 1.44269504088896f

// Scratch (device globals — no allocation allowed). fp16 packed as half2.
__device__ __align__(16) unsigned g_xh[NM*ND/2];        // x fp16 [16384,512]
__device__ __align__(16) unsigned g_wh[4*ND*ND/2];      // weights fp16 (q,k,v,o)
__device__ __align__(16) unsigned g_qkv[3*QSZW];        // Q|K|V [B,H,S,DH]
__device__ __align__(16) unsigned g_oh[NM*ND/2];        // attn out fp16 [B*S,512]

__device__ __forceinline__ void mma_f16(
    float& d0, float& d1, float& d2, float& d3,
    unsigned a0, unsigned a1, unsigned a2, unsigned a3,
    unsigned b0, unsigned b1)
{
    asm volatile(
        "mma.sync.aligned.m16n8k16.row.col.f32.f16.f16.f32 "
        "{%0,%1,%2,%3}, {%4,%5,%6,%7}, {%8,%9}, {%0,%1,%2,%3};\n"
        : "+f"(d0), "+f"(d1), "+f"(d2), "+f"(d3)
        : "r"(a0), "r"(a1), "r"(a2), "r"(a3), "r"(b0), "r"(b1));
}
__device__ __forceinline__ void ldsm_x4(
    unsigned& r0, unsigned& r1, unsigned& r2, unsigned& r3, unsigned addr)
{
    asm volatile("ldmatrix.sync.aligned.m8n8.x4.shared.b16 {%0,%1,%2,%3}, [%4];"
        : "=r"(r0), "=r"(r1), "=r"(r2), "=r"(r3) : "r"(addr));
}
__device__ __forceinline__ void ldsm_x4_t(
    unsigned& r0, unsigned& r1, unsigned& r2, unsigned& r3, unsigned addr)
{
    asm volatile("ldmatrix.sync.aligned.m8n8.x4.trans.shared.b16 {%0,%1,%2,%3}, [%4];"
        : "=r"(r0), "=r"(r1), "=r"(r2), "=r"(r3) : "r"(addr));
}
__device__ __forceinline__ void cp16(unsigned dst, const void* src) {
    asm volatile("cp.async.cg.shared.global [%0], [%1], 16;" :: "r"(dst), "l"(src));
}

// ---------------------------------------------------------------------------
// Prep: f32 -> fp16, single flat launch covering x and all four weights.
// Segment layout: [0, xn4) -> x ; [xn4 + k*wn4, ...) -> weight k.
// ---------------------------------------------------------------------------
__global__ __launch_bounds__(256) void cvt_all(
    const float4* __restrict__ x,
    const float4* __restrict__ wq, const float4* __restrict__ wk,
    const float4* __restrict__ wv, const float4* __restrict__ wo,
    uint2* __restrict__ xh, uint2* __restrict__ wh,
    int xn4, int wn4)
{
    int i = blockIdx.x * 256 + threadIdx.x;
    const float4* src;
    uint2* dst;
    if (i < xn4) {
        src = x + i; dst = xh + i;
    } else {
        int j = i - xn4;
        int widx = j / wn4;
        if (widx >= 4) return;
        int k = j - widx * wn4;
        src = ((widx == 0) ? wq : (widx == 1) ? wk : (widx == 2) ? wv : wo) + k;
        dst = wh + (size_t)widx * wn4 + k;
    }
    float4 v = *src;
    __half2 h01 = __floats2half2_rn(v.x, v.y);
    __half2 h23 = __floats2half2_rn(v.z, v.w);
    *dst = make_uint2(*(unsigned*)&h01, *(unsigned*)&h23);
}

// ---------------------------------------------------------------------------
// Pure fp16 tensor-core GEMM, 2 CTAs/SM. (unchanged from R10/R11)
// ---------------------------------------------------------------------------
#define Q1A_STR 20
#define Q1W_STR 68
#define Q1BUF_A (128*Q1A_STR)
#define Q1BUF_W (32*Q1W_STR)
#define Q1BUF   (Q1BUF_A + Q1BUF_W)
#define Q1SM_WORDS (2*Q1BUF)

__global__ __launch_bounds__(256, 2) void gemm_f16(
    const unsigned* __restrict__ Ahg, const unsigned* __restrict__ Whg,
    void* __restrict__ out, float qscale, int mode)
{
    extern __shared__ unsigned smq[];
    const int t = threadIdx.x;
    const int rbase = blockIdx.x * 128;
    int widx, cbase;
    if (mode == 0) { widx = blockIdx.y >> 2; cbase = (blockIdx.y & 3) * 128; }
    else           { widx = 0; cbase = blockIdx.y * 128; }
    const unsigned* Whp = Whg + (size_t)widx * (ND * ND / 2);
    const float scl = (mode == 0 && widx == 0) ? qscale : 1.0f;
    const int cw0 = cbase >> 1;
    const int w = t >> 5, lane = t & 31;
    const int g = lane >> 2, q = lane & 3;
    const int wm = w >> 1, wn = w & 1;

    unsigned smb;
    asm("{ .reg .u64 x; cvta.to.shared.u64 x, %1; cvt.u32.u64 %0, x; }"
        : "=r"(smb) : "l"(smq));

    const int arow = (lane & 7) + ((lane & 8) ? 8 : 0);
    const int asel = (lane & 16) ? 4 : 0;

    float acc[2][8][4];
    #pragma unroll
    for (int mi = 0; mi < 2; mi++)
        #pragma unroll
        for (int j = 0; j < 8; j++)
            #pragma unroll
            for (int c = 0; c < 4; c++) acc[mi][j][c] = 0.f;

    #pragma unroll
    for (int it = 0; it < 2; it++) {
        int idx = it * 256 + t;
        int r = idx >> 2, c = (idx & 3) * 4;
        cp16(smb + (r * Q1A_STR + c) * 4, Ahg + (size_t)(rbase + r) * 256 + c);
        int rw = idx >> 4, cwt = (idx & 15) * 4;
        cp16(smb + (Q1BUF_A + rw * Q1W_STR + cwt) * 4, Whp + (size_t)rw * 256 + cw0 + cwt);
    }
    asm volatile("cp.async.commit_group;");

    for (int kt = 0; kt < 16; kt++) {
        if (kt < 15) {
            int buf = (kt + 1) & 1;
            #pragma unroll
            for (int it = 0; it < 2; it++) {
                int idx = it * 256 + t;
                int r = idx >> 2, c = (idx & 3) * 4;
                cp16(smb + (buf * Q1BUF + r * Q1A_STR + c) * 4,
                     Ahg + (size_t)(rbase + r) * 256 + (kt + 1) * 16 + c);
                int rw = idx >> 4, cwt = (idx & 15) * 4;
                cp16(smb + (buf * Q1BUF + Q1BUF_A + rw * Q1W_STR + cwt) * 4,
                     Whp + (size_t)((kt + 1) * 32 + rw) * 256 + cw0 + cwt);
            }
            asm volatile("cp.async.commit_group;");
            asm volatile("cp.async.wait_group 1;");
        } else {
            asm volatile("cp.async.wait_group 0;");
        }
        __syncthreads();

        const int buf = kt & 1;
        const unsigned abase = smb + (buf * Q1BUF + (32 * wm + arow) * Q1A_STR + asel) * 4;
        const unsigned bbase = smb + (buf * Q1BUF + Q1BUF_A + arow * Q1W_STR + asel) * 4
                               + wn * 128;
        #pragma unroll
        for (int ks = 0; ks < 2; ks++) {
            unsigned ah[2][4];
            #pragma unroll
            for (int mi = 0; mi < 2; mi++)
                ldsm_x4(ah[mi][0], ah[mi][1], ah[mi][2], ah[mi][3],
                        abase + mi * (16 * Q1A_STR * 4) + ks * 32);
            #pragma unroll
            for (int jp = 0; jp < 4; jp++) {
                unsigned bh0, bh1, bh2, bh3;
                ldsm_x4_t(bh0, bh1, bh2, bh3, bbase + ks * (16 * Q1W_STR * 4) + jp * 32);
                #pragma unroll
                for (int mi = 0; mi < 2; mi++) {
                    float* a0 = acc[mi][2 * jp];
                    float* a1 = acc[mi][2 * jp + 1];
                    mma_f16(a0[0], a0[1], a0[2], a0[3],
                            ah[mi][0], ah[mi][1], ah[mi][2], ah[mi][3], bh0, bh1);
                    mma_f16(a1[0], a1[1], a1[2], a1[3],
                            ah[mi][0], ah[mi][1], ah[mi][2], ah[mi][3], bh2, bh3);
                }
            }
        }
        __syncthreads();
    }

    #pragma unroll
    for (int mi = 0; mi < 2; mi++) {
        #pragma unroll
        for (int j = 0; j < 8; j++) {
            int row0 = rbase + 32 * wm + 16 * mi + g;
            int n = cbase + 64 * wn + 8 * j + 2 * q;
            float v0 = acc[mi][j][0] * scl, v1 = acc[mi][j][1] * scl;
            float v2 = acc[mi][j][2] * scl, v3 = acc[mi][j][3] * scl;
            if (mode == 0) {
                __half2 h0 = __floats2half2_rn(v0, v1);
                __half2 h1 = __floats2half2_rn(v2, v3);
                unsigned* oh = (unsigned*)out + (size_t)widx * QSZW;
                int head = n >> 7, e = n & 127;
                int b0i = row0 >> 12, s0 = row0 & 4095;
                int b1i = (row0 + 8) >> 12, s1 = (row0 + 8) & 4095;
                oh[(((size_t)(b0i * NH + head) * NS + s0) << 6) + (e >> 1)] = *(unsigned*)&h0;
                oh[(((size_t)(b1i * NH + head) * NS + s1) << 6) + (e >> 1)] = *(unsigned*)&h1;
            } else {
                float* of = (float*)out;
                *(float2*)&of[(size_t)row0 * 512 + n] = make_float2(v0, v1);
                *(float2*)&of[(size_t)(row0 + 8) * 512 + n] = make_float2(v2, v3);
            }
        }
    }
}

// ---------------------------------------------------------------------------
// fp16 flash attention — EXACT R11 best (286.4us): no-max log2-domain softmax,
// h2exp2, register-resident P, l via ones-mma, n-half interleaving, 2 CTAs/SM,
// grid 512 heavy-first.
// ---------------------------------------------------------------------------
#define SM2_Q   0
#define SM2_KV  (128*68)
#define KVBUF   (2*64*68)
#define SM2_BIAS (SM2_KV + 2*KVBUF)
#define ATTN_SMEM_WORDS (SM2_BIAS + 256)
#define ONES2 0x3C003C00u

__global__ __launch_bounds__(256, 2) void attn_f16(
    const float* __restrict__ rel_row, const float* __restrict__ rel_col)
{
    extern __shared__ unsigned sm2[];
    const int t = threadIdx.x;
    const int qbx = 31 - blockIdx.x;     // heavy CTAs first
    const int bh = blockIdx.y;
    const int h = bh & 3, b = bh >> 2;
    const int w = t >> 5, lane = t & 31;
    const int g = lane >> 2, q = lane & 3;
    const int base_r = 16 * w;
    const int half_ = (w >= 4) ? 1 : 0;
    const int kb_diag = 2 * qbx + half_;
    const int nkb = 2 * qbx + 2;

    float* srow = (float*)(sm2 + SM2_BIAS);
    float* scol = srow + 128;
    if (t < 128) srow[t] = rel_row[h * 128 + t] * LOG2E;
    else         scol[t - 128] = rel_col[h * 128 + t - 128] * LOG2E;

    const unsigned* Qg  = g_qkv + ((size_t)bh * NS + (size_t)qbx * 128) * 64;
    const unsigned* Kg0 = g_qkv + QSZW + (size_t)bh * NS * 64;
    const unsigned* Vg0 = g_qkv + 2 * QSZW + (size_t)bh * NS * 64;

    #pragma unroll
    for (int it = 0; it < 8; it++) {
        int idx = it * 256 + t;
        int r = idx >> 4, u = (idx & 15) * 4;
        *(uint4*)&sm2[SM2_Q + r * 68 + u] = *(const uint4*)&Qg[r * 64 + u];
    }

    unsigned smb;
    asm("{ .reg .u64 x; cvta.to.shared.u64 x, %1; cvt.u32.u64 %0, x; }"
        : "=r"(smb) : "l"(sm2));

    const int arow = (lane & 7) + ((lane & 8) ? 8 : 0);
    const int asel = (lane & 16) ? 4 : 0;
    const int brow = (lane & 7) + ((lane & 16) ? 8 : 0);
    const int bsel = (lane & 8) ? 4 : 0;
    const unsigned q_ad = smb + (SM2_Q + (base_r + arow) * 68 + asel) * 4;

    {
        #pragma unroll
        for (int it = 0; it < 4; it++) {
            int idx = it * 256 + t;
            int r = idx >> 4, u = (idx & 15) * 4;
            cp16(smb + (SM2_KV + r * 68 + u) * 4, &Kg0[r * 64 + u]);
            cp16(smb + (SM2_KV + 64 * 68 + r * 68 + u) * 4, &Vg0[r * 64 + u]);
        }
        asm volatile("cp.async.commit_group;");
    }

    float lacc[4] = {0.f, 0.f, 0.f, 0.f};
    float oacc[16][4];
    #pragma unroll
    for (int jd = 0; jd < 16; jd++)
        #pragma unroll
        for (int c = 0; c < 4; c++) oacc[jd][c] = 0.f;

    const int qcol0 = (base_r & 63) + g;
    const int qcol1 = qcol0 + 8;

    for (int i = 0; i < nkb; i++) {
        if (i + 1 < nkb) {
            int nb = (i + 1) & 1;
            const unsigned* Kg = Kg0 + (size_t)(i + 1) * 64 * 64;
            const unsigned* Vg = Vg0 + (size_t)(i + 1) * 64 * 64;
            #pragma unroll
            for (int it = 0; it < 4; it++) {
                int idx = it * 256 + t;
                int r = idx >> 4, u = (idx & 15) * 4;
                cp16(smb + (SM2_KV + nb * KVBUF + r * 68 + u) * 4, &Kg[r * 64 + u]);
                cp16(smb + (SM2_KV + nb * KVBUF + 64 * 68 + r * 68 + u) * 4, &Vg[r * 64 + u]);
            }
            asm volatile("cp.async.commit_group;");
            asm volatile("cp.async.wait_group 1;");
        } else {
            asm volatile("cp.async.wait_group 0;");
        }
        __syncthreads();

        if (i <= kb_diag) {
            const int buf = i & 1;
            const unsigned k_ad = smb + (SM2_KV + buf * KVBUF + brow * 68 + bsel) * 4;
            const unsigned v_ad = smb + (SM2_KV + buf * KVBUF + 64 * 68 + arow * 68 + asel) * 4;
            const float rowb = srow[63 + i - kb_diag];
            const bool diag = (i == kb_diag);

            #pragma unroll
            for (int hf = 0; hf < 2; hf++) {
                // ---- S(half) = Q K^T over n-tiles j = 4hf..4hf+3 ----
                float sacc[4][4];
                #pragma unroll
                for (int j = 0; j < 4; j++)
                    #pragma unroll
                    for (int c = 0; c < 4; c++) sacc[j][c] = 0.f;

                #pragma unroll
                for (int ks = 0; ks < 8; ks++) {
                    unsigned a0, a1, a2, a3;
                    ldsm_x4(a0, a1, a2, a3, q_ad + ks * 32);
                    #pragma unroll
                    for (int jp = 0; jp < 2; jp++) {
                        int jpp = 2 * hf + jp;
                        unsigned b0, b1, b2, b3;
                        ldsm_x4(b0, b1, b2, b3, k_ad + jpp * 4352 + ks * 32);
                        mma_f16(sacc[2*jp][0], sacc[2*jp][1], sacc[2*jp][2], sacc[2*jp][3],
                                a0, a1, a2, a3, b0, b1);
                        mma_f16(sacc[2*jp+1][0], sacc[2*jp+1][1], sacc[2*jp+1][2], sacc[2*jp+1][3],
                                a0, a1, a2, a3, b2, b3);
                    }
                }

                // ---- bias + mask + ex2.f16x2; P(half) into A-fragments ----
                unsigned ph0[4], ph1[4];
                #pragma unroll
                for (int j = 0; j < 4; j++) {
                    int jj = 4 * hf + j;
                    int n0 = 8 * jj + 2 * q, n1 = n0 + 1;
                    float s0a = sacc[j][0] + rowb + scol[63 + n0 - qcol0];
                    float s0b = sacc[j][1] + rowb + scol[63 + n1 - qcol0];
                    float s1a = sacc[j][2] + rowb + scol[63 + n0 - qcol1];
                    float s1b = sacc[j][3] + rowb + scol[63 + n1 - qcol1];
                    if (diag) {
                        if (n0 > qcol0) s0a = -60000.f;
                        if (n1 > qcol0) s0b = -60000.f;
                        if (n0 > qcol1) s1a = -60000.f;
                        if (n1 > qcol1) s1b = -60000.f;
                    }
                    __half2 e0 = h2exp2(__floats2half2_rn(s0a, s0b));
                    __half2 e1 = h2exp2(__floats2half2_rn(s1a, s1b));
                    ph0[j] = *(unsigned*)&e0;
                    ph1[j] = *(unsigned*)&e1;
                }

                // ---- O += P V over ks = 2hf, 2hf+1; l += P @ ones ----
                #pragma unroll
                for (int k2 = 0; k2 < 2; k2++) {
                    int ks = 2 * hf + k2;
                    unsigned pa0 = ph0[2*k2], pa1 = ph1[2*k2];
                    unsigned pa2 = ph0[2*k2+1], pa3 = ph1[2*k2+1];
                    mma_f16(lacc[0], lacc[1], lacc[2], lacc[3],
                            pa0, pa1, pa2, pa3, ONES2, ONES2);
                    #pragma unroll
                    for (int jdp = 0; jdp < 8; jdp++) {
                        unsigned vb0, vb1, vb2, vb3;
                        ldsm_x4_t(vb0, vb1, vb2, vb3, v_ad + ks * 4352 + jdp * 32);
                        mma_f16(oacc[2*jdp][0], oacc[2*jdp][1], oacc[2*jdp][2], oacc[2*jdp][3],
                                pa0, pa1, pa2, pa3, vb0, vb1);
                        mma_f16(oacc[2*jdp+1][0], oacc[2*jdp+1][1], oacc[2*jdp+1][2], oacc[2*jdp+1][3],
                                pa0, pa1, pa2, pa3, vb2, vb3);
                    }
                }
            }
        }
        __syncthreads();
    }

    // ---- normalize + fp16 store ----
    const float inv0 = 1.f / lacc[0], inv1 = 1.f / lacc[2];
    const int qg0 = qbx * 128 + base_r + g;
    const int roww0 = ((b * NS + qg0) * ND + h * NDH) >> 1;
    const int roww1 = roww0 + 4 * ND;     // +8 rows
    #pragma unroll
    for (int jd = 0; jd < 16; jd++) {
        __half2 hh0 = __floats2half2_rn(oacc[jd][0] * inv0, oacc[jd][1] * inv0);
        __half2 hh1 = __floats2half2_rn(oacc[jd][2] * inv1, oacc[jd][3] * inv1);
        g_oh[roww0 + 4 * jd + q] = *(unsigned*)&hh0;
        g_oh[roww1 + 4 * jd + q] = *(unsigned*)&hh1;
    }
}

// ---------------------------------------------------------------------------
extern "C" void kernel_launch(void* const* d_in, const int* in_sizes, int n_in,
                              void* d_out, int out_size)
{
    const float* x       = (const float*)d_in[0];
    const float* wq      = (const float*)d_in[1];
    const float* wk      = (const float*)d_in[2];
    const float* wv      = (const float*)d_in[3];
    const float* wo      = (const float*)d_in[4];
    const float* rel_row = (const float*)d_in[5];
    const float* rel_col = (const float*)d_in[6];
    float* out = (float*)d_out;

    unsigned *xh, *wh, *qkv, *oh;
    cudaGetSymbolAddress((void**)&xh, g_xh);
    cudaGetSymbolAddress((void**)&wh, g_wh);
    cudaGetSymbolAddress((void**)&qkv, g_qkv);
    cudaGetSymbolAddress((void**)&oh, g_oh);

    static int smem_set = 0;
    if (!smem_set) {
        cudaFuncSetAttribute(attn_f16, cudaFuncAttributeMaxDynamicSharedMemorySize,
                             ATTN_SMEM_WORDS * (int)sizeof(unsigned));
        cudaFuncSetAttribute(gemm_f16, cudaFuncAttributeMaxDynamicSharedMemorySize,
                             Q1SM_WORDS * (int)sizeof(unsigned));
        smem_set = 1;
    }

    const int WW = ND * ND / 2;
    const int xn4 = NM * ND / 4;          // 2097152
    const int wn4 = ND * ND / 4;          // 65536
    const int tot4 = xn4 + 4 * wn4;       // 2359296

    cvt_all<<<(tot4 + 255) / 256, 256>>>(
        (const float4*)x, (const float4*)wq, (const float4*)wk,
        (const float4*)wv, (const float4*)wo,
        (uint2*)xh, (uint2*)wh, xn4, wn4);

    const float qscale = 0.08838834764831845f * LOG2E;  // 1/sqrt(128) * log2(e)
    size_t gsmem = Q1SM_WORDS * sizeof(unsigned);

    gemm_f16<<<dim3(NM / 128, 12), 256, gsmem>>>(xh, wh, qkv, qscale, 0);

    attn_f16<<<dim3(NS / 128, NB * NH), 256,
               ATTN_SMEM_WORDS * sizeof(unsigned)>>>(rel_row, rel_col);

    gemm_f16<<<dim3(NM / 128, 4), 256, gsmem>>>(oh, wh + 3 * WW, out, 1.0f, 1);
}

// round 16
// speedup vs baseline: 1.3742x; 1.0082x over previous
#include <cuda_runtime.h>
#include <cuda_fp16.h>
#include <math.h>

// Problem constants
#define NB 4
#define NH 4
#define NS 4096
#define NDH 128
#define ND 512
#define NM (NB*NS)
#define QSZW (NB*NH*NS*NDH/2)   // words per Q/K/V tensor

#define LOG2E 1.44269504088896f

// Scratch (device globals — no allocation allowed). fp16 packed as half2.
__device__ __align__(16) unsigned g_xh[NM*ND/2];        // x fp16 [16384,512]
__device__ __align__(16) unsigned g_wh[4*ND*ND/2];      // weights fp16 (q,k,v,o)
__device__ __align__(16) unsigned g_qkv[3*QSZW];        // Q|K|V [B,H,S,DH]
__device__ __align__(16) unsigned g_oh[NM*ND/2];        // attn out fp16 [B*S,512]

__device__ __forceinline__ void mma_f16(
    float& d0, float& d1, float& d2, float& d3,
    unsigned a0, unsigned a1, unsigned a2, unsigned a3,
    unsigned b0, unsigned b1)
{
    asm volatile(
        "mma.sync.aligned.m16n8k16.row.col.f32.f16.f16.f32 "
        "{%0,%1,%2,%3}, {%4,%5,%6,%7}, {%8,%9}, {%0,%1,%2,%3};\n"
        : "+f"(d0), "+f"(d1), "+f"(d2), "+f"(d3)
        : "r"(a0), "r"(a1), "r"(a2), "r"(a3), "r"(b0), "r"(b1));
}
__device__ __forceinline__ void ldsm_x4(
    unsigned& r0, unsigned& r1, unsigned& r2, unsigned& r3, unsigned addr)
{
    asm volatile("ldmatrix.sync.aligned.m8n8.x4.shared.b16 {%0,%1,%2,%3}, [%4];"
        : "=r"(r0), "=r"(r1), "=r"(r2), "=r"(r3) : "r"(addr));
}
__device__ __forceinline__ void ldsm_x4_t(
    unsigned& r0, unsigned& r1, unsigned& r2, unsigned& r3, unsigned addr)
{
    asm volatile("ldmatrix.sync.aligned.m8n8.x4.trans.shared.b16 {%0,%1,%2,%3}, [%4];"
        : "=r"(r0), "=r"(r1), "=r"(r2), "=r"(r3) : "r"(addr));
}
__device__ __forceinline__ void cp16(unsigned dst, const void* src) {
    asm volatile("cp.async.cg.shared.global [%0], [%1], 16;" :: "r"(dst), "l"(src));
}

// ---------------------------------------------------------------------------
// Prep: f32 -> fp16, single flat launch covering x and all four weights.
// ---------------------------------------------------------------------------
__global__ __launch_bounds__(256) void cvt_all(
    const float4* __restrict__ x,
    const float4* __restrict__ wq, const float4* __restrict__ wk,
    const float4* __restrict__ wv, const float4* __restrict__ wo,
    uint2* __restrict__ xh, uint2* __restrict__ wh,
    int xn4, int wn4)
{
    int i = blockIdx.x * 256 + threadIdx.x;
    const float4* src;
    uint2* dst;
    if (i < xn4) {
        src = x + i; dst = xh + i;
    } else {
        int j = i - xn4;
        int widx = j / wn4;
        if (widx >= 4) return;
        int k = j - widx * wn4;
        src = ((widx == 0) ? wq : (widx == 1) ? wk : (widx == 2) ? wv : wo) + k;
        dst = wh + (size_t)widx * wn4 + k;
    }
    float4 v = *src;
    __half2 h01 = __floats2half2_rn(v.x, v.y);
    __half2 h23 = __floats2half2_rn(v.z, v.w);
    *dst = make_uint2(*(unsigned*)&h01, *(unsigned*)&h23);
}

// ---------------------------------------------------------------------------
// Pure fp16 tensor-core GEMM, 2 CTAs/SM, 3-STAGE cp.async pipeline:
// wait -> single __syncthreads -> fetch(kt+2) -> compute(kt).
// Prefetch distance 2 iterations, one barrier per iteration.
// ---------------------------------------------------------------------------
#define Q1A_STR 20
#define Q1W_STR 68
#define Q1BUF_A (128*Q1A_STR)
#define Q1BUF_W (32*Q1W_STR)
#define Q1BUF   (Q1BUF_A + Q1BUF_W)
#define Q1SM_WORDS (3*Q1BUF)

__global__ __launch_bounds__(256, 2) void gemm_f16(
    const unsigned* __restrict__ Ahg, const unsigned* __restrict__ Whg,
    void* __restrict__ out, float qscale, int mode)
{
    extern __shared__ unsigned smq[];
    const int t = threadIdx.x;
    const int rbase = blockIdx.x * 128;
    int widx, cbase;
    if (mode == 0) { widx = blockIdx.y >> 2; cbase = (blockIdx.y & 3) * 128; }
    else           { widx = 0; cbase = blockIdx.y * 128; }
    const unsigned* Whp = Whg + (size_t)widx * (ND * ND / 2);
    const float scl = (mode == 0 && widx == 0) ? qscale : 1.0f;
    const int cw0 = cbase >> 1;
    const int w = t >> 5, lane = t & 31;
    const int g = lane >> 2, q = lane & 3;
    const int wm = w >> 1, wn = w & 1;

    unsigned smb;
    asm("{ .reg .u64 x; cvta.to.shared.u64 x, %1; cvt.u32.u64 %0, x; }"
        : "=r"(smb) : "l"(smq));

    const int arow = (lane & 7) + ((lane & 8) ? 8 : 0);
    const int asel = (lane & 16) ? 4 : 0;

    float acc[2][8][4];
    #pragma unroll
    for (int mi = 0; mi < 2; mi++)
        #pragma unroll
        for (int j = 0; j < 8; j++)
            #pragma unroll
            for (int c = 0; c < 4; c++) acc[mi][j][c] = 0.f;

    // prologue: stage chunks 0 and 1 into buffers 0 and 1
    #pragma unroll
    for (int c = 0; c < 2; c++) {
        #pragma unroll
        for (int it = 0; it < 2; it++) {
            int idx = it * 256 + t;
            int r = idx >> 2, cc = (idx & 3) * 4;
            cp16(smb + (c * Q1BUF + r * Q1A_STR + cc) * 4,
                 Ahg + (size_t)(rbase + r) * 256 + c * 16 + cc);
            int rw = idx >> 4, cwt = (idx & 15) * 4;
            cp16(smb + (c * Q1BUF + Q1BUF_A + rw * Q1W_STR + cwt) * 4,
                 Whp + (size_t)(c * 32 + rw) * 256 + cw0 + cwt);
        }
        asm volatile("cp.async.commit_group;");
    }

    for (int kt = 0; kt < 16; kt++) {
        if (kt < 15) asm volatile("cp.async.wait_group 1;");
        else         asm volatile("cp.async.wait_group 0;");
        __syncthreads();

        if (kt + 2 < 16) {
            int nb = (kt + 2) % 3;
            #pragma unroll
            for (int it = 0; it < 2; it++) {
                int idx = it * 256 + t;
                int r = idx >> 2, cc = (idx & 3) * 4;
                cp16(smb + (nb * Q1BUF + r * Q1A_STR + cc) * 4,
                     Ahg + (size_t)(rbase + r) * 256 + (kt + 2) * 16 + cc);
                int rw = idx >> 4, cwt = (idx & 15) * 4;
                cp16(smb + (nb * Q1BUF + Q1BUF_A + rw * Q1W_STR + cwt) * 4,
                     Whp + (size_t)((kt + 2) * 32 + rw) * 256 + cw0 + cwt);
            }
            asm volatile("cp.async.commit_group;");
        }

        const int buf = kt % 3;
        const unsigned abase = smb + (buf * Q1BUF + (32 * wm + arow) * Q1A_STR + asel) * 4;
        const unsigned bbase = smb + (buf * Q1BUF + Q1BUF_A + arow * Q1W_STR + asel) * 4
                               + wn * 128;
        #pragma unroll
        for (int ks = 0; ks < 2; ks++) {
            unsigned ah[2][4];
            #pragma unroll
            for (int mi = 0; mi < 2; mi++)
                ldsm_x4(ah[mi][0], ah[mi][1], ah[mi][2], ah[mi][3],
                        abase + mi * (16 * Q1A_STR * 4) + ks * 32);
            #pragma unroll
            for (int jp = 0; jp < 4; jp++) {
                unsigned bh0, bh1, bh2, bh3;
                ldsm_x4_t(bh0, bh1, bh2, bh3, bbase + ks * (16 * Q1W_STR * 4) + jp * 32);
                #pragma unroll
                for (int mi = 0; mi < 2; mi++) {
                    float* a0 = acc[mi][2 * jp];
                    float* a1 = acc[mi][2 * jp + 1];
                    mma_f16(a0[0], a0[1], a0[2], a0[3],
                            ah[mi][0], ah[mi][1], ah[mi][2], ah[mi][3], bh0, bh1);
                    mma_f16(a1[0], a1[1], a1[2], a1[3],
                            ah[mi][0], ah[mi][1], ah[mi][2], ah[mi][3], bh2, bh3);
                }
            }
        }
    }

    #pragma unroll
    for (int mi = 0; mi < 2; mi++) {
        #pragma unroll
        for (int j = 0; j < 8; j++) {
            int row0 = rbase + 32 * wm + 16 * mi + g;
            int n = cbase + 64 * wn + 8 * j + 2 * q;
            float v0 = acc[mi][j][0] * scl, v1 = acc[mi][j][1] * scl;
            float v2 = acc[mi][j][2] * scl, v3 = acc[mi][j][3] * scl;
            if (mode == 0) {
                __half2 h0 = __floats2half2_rn(v0, v1);
                __half2 h1 = __floats2half2_rn(v2, v3);
                unsigned* oh = (unsigned*)out + (size_t)widx * QSZW;
                int head = n >> 7, e = n & 127;
                int b0i = row0 >> 12, s0 = row0 & 4095;
                int b1i = (row0 + 8) >> 12, s1 = (row0 + 8) & 4095;
                oh[(((size_t)(b0i * NH + head) * NS + s0) << 6) + (e >> 1)] = *(unsigned*)&h0;
                oh[(((size_t)(b1i * NH + head) * NS + s1) << 6) + (e >> 1)] = *(unsigned*)&h1;
            } else {
                float* of = (float*)out;
                *(float2*)&of[(size_t)row0 * 512 + n] = make_float2(v0, v1);
                *(float2*)&of[(size_t)(row0 + 8) * 512 + n] = make_float2(v2, v3);
            }
        }
    }
}

// ---------------------------------------------------------------------------
// fp16 flash attention — EXACT R11/R15 best (286.4us).
// ---------------------------------------------------------------------------
#define SM2_Q   0
#define SM2_KV  (128*68)
#define KVBUF   (2*64*68)
#define SM2_BIAS (SM2_KV + 2*KVBUF)
#define ATTN_SMEM_WORDS (SM2_BIAS + 256)
#define ONES2 0x3C003C00u

__global__ __launch_bounds__(256, 2) void attn_f16(
    const float* __restrict__ rel_row, const float* __restrict__ rel_col)
{
    extern __shared__ unsigned sm2[];
    const int t = threadIdx.x;
    const int qbx = 31 - blockIdx.x;     // heavy CTAs first
    const int bh = blockIdx.y;
    const int h = bh & 3, b = bh >> 2;
    const int w = t >> 5, lane = t & 31;
    const int g = lane >> 2, q = lane & 3;
    const int base_r = 16 * w;
    const int half_ = (w >= 4) ? 1 : 0;
    const int kb_diag = 2 * qbx + half_;
    const int nkb = 2 * qbx + 2;

    float* srow = (float*)(sm2 + SM2_BIAS);
    float* scol = srow + 128;
    if (t < 128) srow[t] = rel_row[h * 128 + t] * LOG2E;
    else         scol[t - 128] = rel_col[h * 128 + t - 128] * LOG2E;

    const unsigned* Qg  = g_qkv + ((size_t)bh * NS + (size_t)qbx * 128) * 64;
    const unsigned* Kg0 = g_qkv + QSZW + (size_t)bh * NS * 64;
    const unsigned* Vg0 = g_qkv + 2 * QSZW + (size_t)bh * NS * 64;

    #pragma unroll
    for (int it = 0; it < 8; it++) {
        int idx = it * 256 + t;
        int r = idx >> 4, u = (idx & 15) * 4;
        *(uint4*)&sm2[SM2_Q + r * 68 + u] = *(const uint4*)&Qg[r * 64 + u];
    }

    unsigned smb;
    asm("{ .reg .u64 x; cvta.to.shared.u64 x, %1; cvt.u32.u64 %0, x; }"
        : "=r"(smb) : "l"(sm2));

    const int arow = (lane & 7) + ((lane & 8) ? 8 : 0);
    const int asel = (lane & 16) ? 4 : 0;
    const int brow = (lane & 7) + ((lane & 16) ? 8 : 0);
    const int bsel = (lane & 8) ? 4 : 0;
    const unsigned q_ad = smb + (SM2_Q + (base_r + arow) * 68 + asel) * 4;

    {
        #pragma unroll
        for (int it = 0; it < 4; it++) {
            int idx = it * 256 + t;
            int r = idx >> 4, u = (idx & 15) * 4;
            cp16(smb + (SM2_KV + r * 68 + u) * 4, &Kg0[r * 64 + u]);
            cp16(smb + (SM2_KV + 64 * 68 + r * 68 + u) * 4, &Vg0[r * 64 + u]);
        }
        asm volatile("cp.async.commit_group;");
    }

    float lacc[4] = {0.f, 0.f, 0.f, 0.f};
    float oacc[16][4];
    #pragma unroll
    for (int jd = 0; jd < 16; jd++)
        #pragma unroll
        for (int c = 0; c < 4; c++) oacc[jd][c] = 0.f;

    const int qcol0 = (base_r & 63) + g;
    const int qcol1 = qcol0 + 8;

    for (int i = 0; i < nkb; i++) {
        if (i + 1 < nkb) {
            int nb = (i + 1) & 1;
            const unsigned* Kg = Kg0 + (size_t)(i + 1) * 64 * 64;
            const unsigned* Vg = Vg0 + (size_t)(i + 1) * 64 * 64;
            #pragma unroll
            for (int it = 0; it < 4; it++) {
                int idx = it * 256 + t;
                int r = idx >> 4, u = (idx & 15) * 4;
                cp16(smb + (SM2_KV + nb * KVBUF + r * 68 + u) * 4, &Kg[r * 64 + u]);
                cp16(smb + (SM2_KV + nb * KVBUF + 64 * 68 + r * 68 + u) * 4, &Vg[r * 64 + u]);
            }
            asm volatile("cp.async.commit_group;");
            asm volatile("cp.async.wait_group 1;");
        } else {
            asm volatile("cp.async.wait_group 0;");
        }
        __syncthreads();

        if (i <= kb_diag) {
            const int buf = i & 1;
            const unsigned k_ad = smb + (SM2_KV + buf * KVBUF + brow * 68 + bsel) * 4;
            const unsigned v_ad = smb + (SM2_KV + buf * KVBUF + 64 * 68 + arow * 68 + asel) * 4;
            const float rowb = srow[63 + i - kb_diag];
            const bool diag = (i == kb_diag);

            #pragma unroll
            for (int hf = 0; hf < 2; hf++) {
                float sacc[4][4];
                #pragma unroll
                for (int j = 0; j < 4; j++)
                    #pragma unroll
                    for (int c = 0; c < 4; c++) sacc[j][c] = 0.f;

                #pragma unroll
                for (int ks = 0; ks < 8; ks++) {
                    unsigned a0, a1, a2, a3;
                    ldsm_x4(a0, a1, a2, a3, q_ad + ks * 32);
                    #pragma unroll
                    for (int jp = 0; jp < 2; jp++) {
                        int jpp = 2 * hf + jp;
                        unsigned b0, b1, b2, b3;
                        ldsm_x4(b0, b1, b2, b3, k_ad + jpp * 4352 + ks * 32);
                        mma_f16(sacc[2*jp][0], sacc[2*jp][1], sacc[2*jp][2], sacc[2*jp][3],
                                a0, a1, a2, a3, b0, b1);
                        mma_f16(sacc[2*jp+1][0], sacc[2*jp+1][1], sacc[2*jp+1][2], sacc[2*jp+1][3],
                                a0, a1, a2, a3, b2, b3);
                    }
                }

                unsigned ph0[4], ph1[4];
                #pragma unroll
                for (int j = 0; j < 4; j++) {
                    int jj = 4 * hf + j;
                    int n0 = 8 * jj + 2 * q, n1 = n0 + 1;
                    float s0a = sacc[j][0] + rowb + scol[63 + n0 - qcol0];
                    float s0b = sacc[j][1] + rowb + scol[63 + n1 - qcol0];
                    float s1a = sacc[j][2] + rowb + scol[63 + n0 - qcol1];
                    float s1b = sacc[j][3] + rowb + scol[63 + n1 - qcol1];
                    if (diag) {
                        if (n0 > qcol0) s0a = -60000.f;
                        if (n1 > qcol0) s0b = -60000.f;
                        if (n0 > qcol1) s1a = -60000.f;
                        if (n1 > qcol1) s1b = -60000.f;
                    }
                    __half2 e0 = h2exp2(__floats2half2_rn(s0a, s0b));
                    __half2 e1 = h2exp2(__floats2half2_rn(s1a, s1b));
                    ph0[j] = *(unsigned*)&e0;
                    ph1[j] = *(unsigned*)&e1;
                }

                #pragma unroll
                for (int k2 = 0; k2 < 2; k2++) {
                    int ks = 2 * hf + k2;
                    unsigned pa0 = ph0[2*k2], pa1 = ph1[2*k2];
                    unsigned pa2 = ph0[2*k2+1], pa3 = ph1[2*k2+1];
                    mma_f16(lacc[0], lacc[1], lacc[2], lacc[3],
                            pa0, pa1, pa2, pa3, ONES2, ONES2);
                    #pragma unroll
                    for (int jdp = 0; jdp < 8; jdp++) {
                        unsigned vb0, vb1, vb2, vb3;
                        ldsm_x4_t(vb0, vb1, vb2, vb3, v_ad + ks * 4352 + jdp * 32);
                        mma_f16(oacc[2*jdp][0], oacc[2*jdp][1], oacc[2*jdp][2], oacc[2*jdp][3],
                                pa0, pa1, pa2, pa3, vb0, vb1);
                        mma_f16(oacc[2*jdp+1][0], oacc[2*jdp+1][1], oacc[2*jdp+1][2], oacc[2*jdp+1][3],
                                pa0, pa1, pa2, pa3, vb2, vb3);
                    }
                }
            }
        }
        __syncthreads();
    }

    const float inv0 = 1.f / lacc[0], inv1 = 1.f / lacc[2];
    const int qg0 = qbx * 128 + base_r + g;
    const int roww0 = ((b * NS + qg0) * ND + h * NDH) >> 1;
    const int roww1 = roww0 + 4 * ND;
    #pragma unroll
    for (int jd = 0; jd < 16; jd++) {
        __half2 hh0 = __floats2half2_rn(oacc[jd][0] * inv0, oacc[jd][1] * inv0);
        __half2 hh1 = __floats2half2_rn(oacc[jd][2] * inv1, oacc[jd][3] * inv1);
        g_oh[roww0 + 4 * jd + q] = *(unsigned*)&hh0;
        g_oh[roww1 + 4 * jd + q] = *(unsigned*)&hh1;
    }
}

// ---------------------------------------------------------------------------
extern "C" void kernel_launch(void* const* d_in, const int* in_sizes, int n_in,
                              void* d_out, int out_size)
{
    const float* x       = (const float*)d_in[0];
    const float* wq      = (const float*)d_in[1];
    const float* wk      = (const float*)d_in[2];
    const float* wv      = (const float*)d_in[3];
    const float* wo      = (const float*)d_in[4];
    const float* rel_row = (const float*)d_in[5];
    const float* rel_col = (const float*)d_in[6];
    float* out = (float*)d_out;

    unsigned *xh, *wh, *qkv, *oh;
    cudaGetSymbolAddress((void**)&xh, g_xh);
    cudaGetSymbolAddress((void**)&wh, g_wh);
    cudaGetSymbolAddress((void**)&qkv, g_qkv);
    cudaGetSymbolAddress((void**)&oh, g_oh);

    static int smem_set = 0;
    if (!smem_set) {
        cudaFuncSetAttribute(attn_f16, cudaFuncAttributeMaxDynamicSharedMemorySize,
                             ATTN_SMEM_WORDS * (int)sizeof(unsigned));
        cudaFuncSetAttribute(gemm_f16, cudaFuncAttributeMaxDynamicSharedMemorySize,
                             Q1SM_WORDS * (int)sizeof(unsigned));
        smem_set = 1;
    }

    const int WW = ND * ND / 2;
    const int xn4 = NM * ND / 4;
    const int wn4 = ND * ND / 4;
    const int tot4 = xn4 + 4 * wn4;

    cvt_all<<<(tot4 + 255) / 256, 256>>>(
        (const float4*)x, (const float4*)wq, (const float4*)wk,
        (const float4*)wv, (const float4*)wo,
        (uint2*)xh, (uint2*)wh, xn4, wn4);

    const float qscale = 0.08838834764831845f * LOG2E;  // 1/sqrt(128) * log2(e)
    size_t gsmem = Q1SM_WORDS * sizeof(unsigned);

    gemm_f16<<<dim3(NM / 128, 12), 256, gsmem>>>(xh, wh, qkv, qscale, 0);

    attn_f16<<<dim3(NS / 128, NB * NH), 256,
               ATTN_SMEM_WORDS * sizeof(unsigned)>>>(rel_row, rel_col);

    gemm_f16<<<dim3(NM / 128, 4), 256, gsmem>>>(oh, wh + 3 * WW, out, 1.0f, 1);
}

// round 17
// speedup vs baseline: 1.3932x; 1.0138x over previous
#include <cuda_runtime.h>
#include <cuda_fp16.h>
#include <math.h>

// Problem constants
#define NB 4
#define NH 4
#define NS 4096
#define NDH 128
#define ND 512
#define NM (NB*NS)
#define QSZW (NB*NH*NS*NDH/2)   // words per Q/K/V tensor

#define LOG2E 1.44269504088896f

// Scratch (device globals — no allocation allowed). fp16 packed as half2.
__device__ __align__(16) unsigned g_xh[NM*ND/2];        // x fp16 [16384,512]
__device__ __align__(16) unsigned g_wh[4*ND*ND/2];      // weights fp16 (q,k,v,o)
__device__ __align__(16) unsigned g_qkv[3*QSZW];        // Q|K|V [B,H,S,DH]
__device__ __align__(16) unsigned g_oh[NM*ND/2];        // attn out fp16 [B*S,512]

__device__ __forceinline__ void mma_f16(
    float& d0, float& d1, float& d2, float& d3,
    unsigned a0, unsigned a1, unsigned a2, unsigned a3,
    unsigned b0, unsigned b1)
{
    asm volatile(
        "mma.sync.aligned.m16n8k16.row.col.f32.f16.f16.f32 "
        "{%0,%1,%2,%3}, {%4,%5,%6,%7}, {%8,%9}, {%0,%1,%2,%3};\n"
        : "+f"(d0), "+f"(d1), "+f"(d2), "+f"(d3)
        : "r"(a0), "r"(a1), "r"(a2), "r"(a3), "r"(b0), "r"(b1));
}
__device__ __forceinline__ void ldsm_x4(
    unsigned& r0, unsigned& r1, unsigned& r2, unsigned& r3, unsigned addr)
{
    asm volatile("ldmatrix.sync.aligned.m8n8.x4.shared.b16 {%0,%1,%2,%3}, [%4];"
        : "=r"(r0), "=r"(r1), "=r"(r2), "=r"(r3) : "r"(addr));
}
__device__ __forceinline__ void ldsm_x4_t(
    unsigned& r0, unsigned& r1, unsigned& r2, unsigned& r3, unsigned addr)
{
    asm volatile("ldmatrix.sync.aligned.m8n8.x4.trans.shared.b16 {%0,%1,%2,%3}, [%4];"
        : "=r"(r0), "=r"(r1), "=r"(r2), "=r"(r3) : "r"(addr));
}
__device__ __forceinline__ void cp16(unsigned dst, const void* src) {
    asm volatile("cp.async.cg.shared.global [%0], [%1], 16;" :: "r"(dst), "l"(src));
}

// ---------------------------------------------------------------------------
// Prep: f32 -> fp16, single flat launch covering x and all four weights.
// ---------------------------------------------------------------------------
__global__ __launch_bounds__(256) void cvt_all(
    const float4* __restrict__ x,
    const float4* __restrict__ wq, const float4* __restrict__ wk,
    const float4* __restrict__ wv, const float4* __restrict__ wo,
    uint2* __restrict__ xh, uint2* __restrict__ wh,
    int xn4, int wn4)
{
    int i = blockIdx.x * 256 + threadIdx.x;
    const float4* src;
    uint2* dst;
    if (i < xn4) {
        src = x + i; dst = xh + i;
    } else {
        int j = i - xn4;
        int widx = j / wn4;
        if (widx >= 4) return;
        int k = j - widx * wn4;
        src = ((widx == 0) ? wq : (widx == 1) ? wk : (widx == 2) ? wv : wo) + k;
        dst = wh + (size_t)widx * wn4 + k;
    }
    float4 v = *src;
    __half2 h01 = __floats2half2_rn(v.x, v.y);
    __half2 h23 = __floats2half2_rn(v.z, v.w);
    *dst = make_uint2(*(unsigned*)&h01, *(unsigned*)&h23);
}

// ---------------------------------------------------------------------------
// Pure fp16 tensor-core GEMM, 2 CTAs/SM, BK=64, 3-stage cp.async pipeline:
// 8 iterations, one barrier each, distance-2 prefetch.
// ---------------------------------------------------------------------------
#define Q2A_STR 36
#define Q2W_STR 68
#define Q2BUF_A (128*Q2A_STR)      // 4608 words
#define Q2BUF_W (64*Q2W_STR)       // 4352 words
#define Q2BUF   (Q2BUF_A + Q2BUF_W)
#define Q2SM_WORDS (3*Q2BUF)

__global__ __launch_bounds__(256, 2) void gemm_f16(
    const unsigned* __restrict__ Ahg, const unsigned* __restrict__ Whg,
    void* __restrict__ out, float qscale, int mode)
{
    extern __shared__ unsigned smq[];
    const int t = threadIdx.x;
    const int rbase = blockIdx.x * 128;
    int widx, cbase;
    if (mode == 0) { widx = blockIdx.y >> 2; cbase = (blockIdx.y & 3) * 128; }
    else           { widx = 0; cbase = blockIdx.y * 128; }
    const unsigned* Whp = Whg + (size_t)widx * (ND * ND / 2);
    const float scl = (mode == 0 && widx == 0) ? qscale : 1.0f;
    const int cw0 = cbase >> 1;
    const int w = t >> 5, lane = t & 31;
    const int g = lane >> 2, q = lane & 3;
    const int wm = w >> 1, wn = w & 1;

    unsigned smb;
    asm("{ .reg .u64 x; cvta.to.shared.u64 x, %1; cvt.u32.u64 %0, x; }"
        : "=r"(smb) : "l"(smq));

    const int arow = (lane & 7) + ((lane & 8) ? 8 : 0);
    const int asel = (lane & 16) ? 4 : 0;

    float acc[2][8][4];
    #pragma unroll
    for (int mi = 0; mi < 2; mi++)
        #pragma unroll
        for (int j = 0; j < 8; j++)
            #pragma unroll
            for (int c = 0; c < 4; c++) acc[mi][j][c] = 0.f;

    // prologue: stage chunks 0 and 1
    #pragma unroll
    for (int c = 0; c < 2; c++) {
        #pragma unroll
        for (int it = 0; it < 4; it++) {
            int idx = it * 256 + t;
            int r = idx >> 3, cc = (idx & 7) * 4;
            cp16(smb + (c * Q2BUF + r * Q2A_STR + cc) * 4,
                 Ahg + (size_t)(rbase + r) * 256 + c * 32 + cc);
            int rw = idx >> 4, cwt = (idx & 15) * 4;
            cp16(smb + (c * Q2BUF + Q2BUF_A + rw * Q2W_STR + cwt) * 4,
                 Whp + (size_t)(c * 64 + rw) * 256 + cw0 + cwt);
        }
        asm volatile("cp.async.commit_group;");
    }

    for (int kt = 0; kt < 8; kt++) {
        if (kt < 7) asm volatile("cp.async.wait_group 1;");
        else        asm volatile("cp.async.wait_group 0;");
        __syncthreads();

        if (kt + 2 < 8) {
            int nb = (kt + 2) % 3;
            #pragma unroll
            for (int it = 0; it < 4; it++) {
                int idx = it * 256 + t;
                int r = idx >> 3, cc = (idx & 7) * 4;
                cp16(smb + (nb * Q2BUF + r * Q2A_STR + cc) * 4,
                     Ahg + (size_t)(rbase + r) * 256 + (kt + 2) * 32 + cc);
                int rw = idx >> 4, cwt = (idx & 15) * 4;
                cp16(smb + (nb * Q2BUF + Q2BUF_A + rw * Q2W_STR + cwt) * 4,
                     Whp + (size_t)((kt + 2) * 64 + rw) * 256 + cw0 + cwt);
            }
            asm volatile("cp.async.commit_group;");
        }

        const int buf = kt % 3;
        const unsigned abase = smb + (buf * Q2BUF + (32 * wm + arow) * Q2A_STR + asel) * 4;
        const unsigned bbase = smb + (buf * Q2BUF + Q2BUF_A + arow * Q2W_STR + asel) * 4
                               + wn * 128;
        #pragma unroll
        for (int ks = 0; ks < 4; ks++) {
            unsigned ah[2][4];
            #pragma unroll
            for (int mi = 0; mi < 2; mi++)
                ldsm_x4(ah[mi][0], ah[mi][1], ah[mi][2], ah[mi][3],
                        abase + mi * (16 * Q2A_STR * 4) + ks * 32);
            #pragma unroll
            for (int jp = 0; jp < 4; jp++) {
                unsigned bh0, bh1, bh2, bh3;
                ldsm_x4_t(bh0, bh1, bh2, bh3, bbase + ks * (16 * Q2W_STR * 4) + jp * 32);
                #pragma unroll
                for (int mi = 0; mi < 2; mi++) {
                    float* a0 = acc[mi][2 * jp];
                    float* a1 = acc[mi][2 * jp + 1];
                    mma_f16(a0[0], a0[1], a0[2], a0[3],
                            ah[mi][0], ah[mi][1], ah[mi][2], ah[mi][3], bh0, bh1);
                    mma_f16(a1[0], a1[1], a1[2], a1[3],
                            ah[mi][0], ah[mi][1], ah[mi][2], ah[mi][3], bh2, bh3);
                }
            }
        }
    }

    #pragma unroll
    for (int mi = 0; mi < 2; mi++) {
        #pragma unroll
        for (int j = 0; j < 8; j++) {
            int row0 = rbase + 32 * wm + 16 * mi + g;
            int n = cbase + 64 * wn + 8 * j + 2 * q;
            float v0 = acc[mi][j][0] * scl, v1 = acc[mi][j][1] * scl;
            float v2 = acc[mi][j][2] * scl, v3 = acc[mi][j][3] * scl;
            if (mode == 0) {
                __half2 h0 = __floats2half2_rn(v0, v1);
                __half2 h1 = __floats2half2_rn(v2, v3);
                unsigned* oh = (unsigned*)out + (size_t)widx * QSZW;
                int head = n >> 7, e = n & 127;
                int b0i = row0 >> 12, s0 = row0 & 4095;
                int b1i = (row0 + 8) >> 12, s1 = (row0 + 8) & 4095;
                oh[(((size_t)(b0i * NH + head) * NS + s0) << 6) + (e >> 1)] = *(unsigned*)&h0;
                oh[(((size_t)(b1i * NH + head) * NS + s1) << 6) + (e >> 1)] = *(unsigned*)&h1;
            } else {
                float* of = (float*)out;
                *(float2*)&of[(size_t)row0 * 512 + n] = make_float2(v0, v1);
                *(float2*)&of[(size_t)(row0 + 8) * 512 + n] = make_float2(v2, v3);
            }
        }
    }
}

// ---------------------------------------------------------------------------
// fp16 flash attention — EXACT R11/R15 best (286.4us).
// ---------------------------------------------------------------------------
#define SM2_Q   0
#define SM2_KV  (128*68)
#define KVBUF   (2*64*68)
#define SM2_BIAS (SM2_KV + 2*KVBUF)
#define ATTN_SMEM_WORDS (SM2_BIAS + 256)
#define ONES2 0x3C003C00u

__global__ __launch_bounds__(256, 2) void attn_f16(
    const float* __restrict__ rel_row, const float* __restrict__ rel_col)
{
    extern __shared__ unsigned sm2[];
    const int t = threadIdx.x;
    const int qbx = 31 - blockIdx.x;     // heavy CTAs first
    const int bh = blockIdx.y;
    const int h = bh & 3, b = bh >> 2;
    const int w = t >> 5, lane = t & 31;
    const int g = lane >> 2, q = lane & 3;
    const int base_r = 16 * w;
    const int half_ = (w >= 4) ? 1 : 0;
    const int kb_diag = 2 * qbx + half_;
    const int nkb = 2 * qbx + 2;

    float* srow = (float*)(sm2 + SM2_BIAS);
    float* scol = srow + 128;
    if (t < 128) srow[t] = rel_row[h * 128 + t] * LOG2E;
    else         scol[t - 128] = rel_col[h * 128 + t - 128] * LOG2E;

    const unsigned* Qg  = g_qkv + ((size_t)bh * NS + (size_t)qbx * 128) * 64;
    const unsigned* Kg0 = g_qkv + QSZW + (size_t)bh * NS * 64;
    const unsigned* Vg0 = g_qkv + 2 * QSZW + (size_t)bh * NS * 64;

    #pragma unroll
    for (int it = 0; it < 8; it++) {
        int idx = it * 256 + t;
        int r = idx >> 4, u = (idx & 15) * 4;
        *(uint4*)&sm2[SM2_Q + r * 68 + u] = *(const uint4*)&Qg[r * 64 + u];
    }

    unsigned smb;
    asm("{ .reg .u64 x; cvta.to.shared.u64 x, %1; cvt.u32.u64 %0, x; }"
        : "=r"(smb) : "l"(sm2));

    const int arow = (lane & 7) + ((lane & 8) ? 8 : 0);
    const int asel = (lane & 16) ? 4 : 0;
    const int brow = (lane & 7) + ((lane & 16) ? 8 : 0);
    const int bsel = (lane & 8) ? 4 : 0;
    const unsigned q_ad = smb + (SM2_Q + (base_r + arow) * 68 + asel) * 4;

    {
        #pragma unroll
        for (int it = 0; it < 4; it++) {
            int idx = it * 256 + t;
            int r = idx >> 4, u = (idx & 15) * 4;
            cp16(smb + (SM2_KV + r * 68 + u) * 4, &Kg0[r * 64 + u]);
            cp16(smb + (SM2_KV + 64 * 68 + r * 68 + u) * 4, &Vg0[r * 64 + u]);
        }
        asm volatile("cp.async.commit_group;");
    }

    float lacc[4] = {0.f, 0.f, 0.f, 0.f};
    float oacc[16][4];
    #pragma unroll
    for (int jd = 0; jd < 16; jd++)
        #pragma unroll
        for (int c = 0; c < 4; c++) oacc[jd][c] = 0.f;

    const int qcol0 = (base_r & 63) + g;
    const int qcol1 = qcol0 + 8;

    for (int i = 0; i < nkb; i++) {
        if (i + 1 < nkb) {
            int nb = (i + 1) & 1;
            const unsigned* Kg = Kg0 + (size_t)(i + 1) * 64 * 64;
            const unsigned* Vg = Vg0 + (size_t)(i + 1) * 64 * 64;
            #pragma unroll
            for (int it = 0; it < 4; it++) {
                int idx = it * 256 + t;
                int r = idx >> 4, u = (idx & 15) * 4;
                cp16(smb + (SM2_KV + nb * KVBUF + r * 68 + u) * 4, &Kg[r * 64 + u]);
                cp16(smb + (SM2_KV + nb * KVBUF + 64 * 68 + r * 68 + u) * 4, &Vg[r * 64 + u]);
            }
            asm volatile("cp.async.commit_group;");
            asm volatile("cp.async.wait_group 1;");
        } else {
            asm volatile("cp.async.wait_group 0;");
        }
        __syncthreads();

        if (i <= kb_diag) {
            const int buf = i & 1;
            const unsigned k_ad = smb + (SM2_KV + buf * KVBUF + brow * 68 + bsel) * 4;
            const unsigned v_ad = smb + (SM2_KV + buf * KVBUF + 64 * 68 + arow * 68 + asel) * 4;
            const float rowb = srow[63 + i - kb_diag];
            const bool diag = (i == kb_diag);

            #pragma unroll
            for (int hf = 0; hf < 2; hf++) {
                float sacc[4][4];
                #pragma unroll
                for (int j = 0; j < 4; j++)
                    #pragma unroll
                    for (int c = 0; c < 4; c++) sacc[j][c] = 0.f;

                #pragma unroll
                for (int ks = 0; ks < 8; ks++) {
                    unsigned a0, a1, a2, a3;
                    ldsm_x4(a0, a1, a2, a3, q_ad + ks * 32);
                    #pragma unroll
                    for (int jp = 0; jp < 2; jp++) {
                        int jpp = 2 * hf + jp;
                        unsigned b0, b1, b2, b3;
                        ldsm_x4(b0, b1, b2, b3, k_ad + jpp * 4352 + ks * 32);
                        mma_f16(sacc[2*jp][0], sacc[2*jp][1], sacc[2*jp][2], sacc[2*jp][3],
                                a0, a1, a2, a3, b0, b1);
                        mma_f16(sacc[2*jp+1][0], sacc[2*jp+1][1], sacc[2*jp+1][2], sacc[2*jp+1][3],
                                a0, a1, a2, a3, b2, b3);
                    }
                }

                unsigned ph0[4], ph1[4];
                #pragma unroll
                for (int j = 0; j < 4; j++) {
                    int jj = 4 * hf + j;
                    int n0 = 8 * jj + 2 * q, n1 = n0 + 1;
                    float s0a = sacc[j][0] + rowb + scol[63 + n0 - qcol0];
                    float s0b = sacc[j][1] + rowb + scol[63 + n1 - qcol0];
                    float s1a = sacc[j][2] + rowb + scol[63 + n0 - qcol1];
                    float s1b = sacc[j][3] + rowb + scol[63 + n1 - qcol1];
                    if (diag) {
                        if (n0 > qcol0) s0a = -60000.f;
                        if (n1 > qcol0) s0b = -60000.f;
                        if (n0 > qcol1) s1a = -60000.f;
                        if (n1 > qcol1) s1b = -60000.f;
                    }
                    __half2 e0 = h2exp2(__floats2half2_rn(s0a, s0b));
                    __half2 e1 = h2exp2(__floats2half2_rn(s1a, s1b));
                    ph0[j] = *(unsigned*)&e0;
                    ph1[j] = *(unsigned*)&e1;
                }

                #pragma unroll
                for (int k2 = 0; k2 < 2; k2++) {
                    int ks = 2 * hf + k2;
                    unsigned pa0 = ph0[2*k2], pa1 = ph1[2*k2];
                    unsigned pa2 = ph0[2*k2+1], pa3 = ph1[2*k2+1];
                    mma_f16(lacc[0], lacc[1], lacc[2], lacc[3],
                            pa0, pa1, pa2, pa3, ONES2, ONES2);
                    #pragma unroll
                    for (int jdp = 0; jdp < 8; jdp++) {
                        unsigned vb0, vb1, vb2, vb3;
                        ldsm_x4_t(vb0, vb1, vb2, vb3, v_ad + ks * 4352 + jdp * 32);
                        mma_f16(oacc[2*jdp][0], oacc[2*jdp][1], oacc[2*jdp][2], oacc[2*jdp][3],
                                pa0, pa1, pa2, pa3, vb0, vb1);
                        mma_f16(oacc[2*jdp+1][0], oacc[2*jdp+1][1], oacc[2*jdp+1][2], oacc[2*jdp+1][3],
                                pa0, pa1, pa2, pa3, vb2, vb3);
                    }
                }
            }
        }
        __syncthreads();
    }

    const float inv0 = 1.f / lacc[0], inv1 = 1.f / lacc[2];
    const int qg0 = qbx * 128 + base_r + g;
    const int roww0 = ((b * NS + qg0) * ND + h * NDH) >> 1;
    const int roww1 = roww0 + 4 * ND;
    #pragma unroll
    for (int jd = 0; jd < 16; jd++) {
        __half2 hh0 = __floats2half2_rn(oacc[jd][0] * inv0, oacc[jd][1] * inv0);
        __half2 hh1 = __floats2half2_rn(oacc[jd][2] * inv1, oacc[jd][3] * inv1);
        g_oh[roww0 + 4 * jd + q] = *(unsigned*)&hh0;
        g_oh[roww1 + 4 * jd + q] = *(unsigned*)&hh1;
    }
}

// ---------------------------------------------------------------------------
extern "C" void kernel_launch(void* const* d_in, const int* in_sizes, int n_in,
                              void* d_out, int out_size)
{
    const float* x       = (const float*)d_in[0];
    const float* wq      = (const float*)d_in[1];
    const float* wk      = (const float*)d_in[2];
    const float* wv      = (const float*)d_in[3];
    const float* wo      = (const float*)d_in[4];
    const float* rel_row = (const float*)d_in[5];
    const float* rel_col = (const float*)d_in[6];
    float* out = (float*)d_out;

    unsigned *xh, *wh, *qkv, *oh;
    cudaGetSymbolAddress((void**)&xh, g_xh);
    cudaGetSymbolAddress((void**)&wh, g_wh);
    cudaGetSymbolAddress((void**)&qkv, g_qkv);
    cudaGetSymbolAddress((void**)&oh, g_oh);

    static int smem_set = 0;
    if (!smem_set) {
        cudaFuncSetAttribute(attn_f16, cudaFuncAttributeMaxDynamicSharedMemorySize,
                             ATTN_SMEM_WORDS * (int)sizeof(unsigned));
        cudaFuncSetAttribute(gemm_f16, cudaFuncAttributeMaxDynamicSharedMemorySize,
                             Q2SM_WORDS * (int)sizeof(unsigned));
        smem_set = 1;
    }

    const int WW = ND * ND / 2;
    const int xn4 = NM * ND / 4;
    const int wn4 = ND * ND / 4;
    const int tot4 = xn4 + 4 * wn4;

    cvt_all<<<(tot4 + 255) / 256, 256>>>(
        (const float4*)x, (const float4*)wq, (const float4*)wk,
        (const float4*)wv, (const float4*)wo,
        (uint2*)xh, (uint2*)wh, xn4, wn4);

    const float qscale = 0.08838834764831845f * LOG2E;  // 1/sqrt(128) * log2(e)
    size_t gsmem = Q2SM_WORDS * sizeof(unsigned);

    gemm_f16<<<dim3(NM / 128, 12), 256, gsmem>>>(xh, wh, qkv, qscale, 0);

    attn_f16<<<dim3(NS / 128, NB * NH), 256,
               ATTN_SMEM_WORDS * sizeof(unsigned)>>>(rel_row, rel_col);

    gemm_f16<<<dim3(NM / 128, 4), 256, gsmem>>>(oh, wh + 3 * WW, out, 1.0f, 1);
}